// round 7
// baseline (speedup 1.0000x reference)
#include <cuda_runtime.h>
#include <math.h>

#define NN 50000
#define EE 800000
#define ETOT (EE + NN)
#define GG 64

// ---------------- scratch ----------------
__device__ float d_h[NN * 96];
__device__ float d_o[NN * 96];
__device__ float d_as[NN * 4];
__device__ float d_ad[NN * 4];
__device__ int   d_deg[NN];
__device__ int   d_part[NN];
__device__ int   d_bsum[64];
__device__ int   d_off[NN + 1];
__device__ int   d_srcs[ETOT];
__device__ float d_gate[NN];
__device__ float d_ge[NN];
__device__ float d_gm[GG];
__device__ float d_gden[GG];
__device__ float d_pool[GG * 8 * 96];   // per-part partials, no atomics

__device__ __forceinline__ void atomicMaxF(float* a, float v) {
    if (v >= 0.f) atomicMax((int*)a, __float_as_int(v));
    else          atomicMin((unsigned int*)a, __float_as_uint(v));
}

typedef unsigned long long ull;
__device__ __forceinline__ ull pk2(float x, float y) {
    ull r;
    asm("mov.b64 %0, {%1, %2};" : "=l"(r) : "f"(x), "f"(y));
    return r;
}
__device__ __forceinline__ ull fma2(ull a, ull b, ull c) {
    ull d;
    asm("fma.rn.f32x2 %0, %1, %2, %3;" : "=l"(d) : "l"(a), "l"(b), "l"(c));
    return d;
}
__device__ __forceinline__ void upk2(ull v, float& x, float& y) {
    asm("mov.b64 {%0, %1}, %2;" : "=f"(x), "=f"(y) : "l"(v));
}

// ================= CSR build =================
__global__ void k_hist(const int* __restrict__ ei, int* __restrict__ deg, int etot, int eraw) {
    int e = blockIdx.x * blockDim.x + threadIdx.x;
    if (e >= etot) return;
    int d = (e < eraw) ? __ldg(&ei[eraw + e]) : e - eraw;
    atomicAdd(&deg[d], 1);
}

__global__ void k_scanA(const int* __restrict__ deg, int* __restrict__ part,
                        int* __restrict__ bsum, int n) {
    __shared__ int wsum[32];
    int t = threadIdx.x;
    int i = blockIdx.x * 1024 + t;
    int v = (i < n) ? deg[i] : 0;
    int lane = t & 31, w = t >> 5;
    int x = v;
#pragma unroll
    for (int o = 1; o < 32; o <<= 1) {
        int y = __shfl_up_sync(0xffffffffu, x, o);
        if (lane >= o) x += y;
    }
    if (lane == 31) wsum[w] = x;
    __syncthreads();
    if (w == 0) {
        int s = wsum[lane];
#pragma unroll
        for (int o = 1; o < 32; o <<= 1) {
            int y = __shfl_up_sync(0xffffffffu, s, o);
            if (lane >= o) s += y;
        }
        wsum[lane] = s;
    }
    __syncthreads();
    int woff = (w > 0) ? wsum[w - 1] : 0;
    if (i < n) part[i] = x - v + woff;
    if (t == 0) bsum[blockIdx.x] = wsum[31];
}

__global__ void k_scanB(int* __restrict__ bsum, int nb) {
    __shared__ int w0tot;
    int t = threadIdx.x;              // 64 threads
    int lane = t & 31, w = t >> 5;
    int v = (t < nb) ? bsum[t] : 0;
    int x = v;
#pragma unroll
    for (int o = 1; o < 32; o <<= 1) {
        int y = __shfl_up_sync(0xffffffffu, x, o);
        if (lane >= o) x += y;
    }
    if (w == 0 && lane == 31) w0tot = x;
    __syncthreads();
    if (w == 1) x += w0tot;
    if (t < nb) bsum[t] = x - v;
}

// stage C: final offsets + cursor copy + GM/GDEN init (piggyback)
__global__ void k_scanC(const int* __restrict__ part, const int* __restrict__ bsum,
                        int* __restrict__ off, int* __restrict__ cur,
                        float* __restrict__ GM, float* __restrict__ GDEN,
                        int n, int etot) {
    int i = blockIdx.x * 1024 + threadIdx.x;
    if (i < n) {
        int v = part[i] + bsum[blockIdx.x];
        off[i] = v;
        cur[i] = v;
    }
    if (i == 0) off[n] = etot;
    if (blockIdx.x == 0 && threadIdx.x < GG) {
        GM[threadIdx.x] = -INFINITY;
        GDEN[threadIdx.x] = 0.f;
    }
}

__global__ void k_scatter(const int* __restrict__ ei, int* __restrict__ cur,
                          int* __restrict__ srcs, int etot, int eraw) {
    int e = blockIdx.x * blockDim.x + threadIdx.x;
    if (e >= etot) return;
    int s, d;
    if (e < eraw) { s = __ldg(&ei[e]); d = __ldg(&ei[eraw + e]); }
    else          { s = d = e - eraw; }
    int pos = atomicAdd(&cur[d], 1);
    srcs[pos] = s;
}

// ================= GEMM + fused alpha epilogue =================
template<int K, int KC>
__global__ void __launch_bounds__(384, 2) k_gemm2(const float* __restrict__ A,
                                                  const float* __restrict__ W,
                                                  const float* __restrict__ asrc,
                                                  const float* __restrict__ adst,
                                                  float* __restrict__ H,
                                                  float* __restrict__ AS,
                                                  float* __restrict__ AD, int n) {
    extern __shared__ float sm[];
    float* Bs = sm;              // K*96 (full weights, global-k)
    float* As = sm + K * 96;     // KC*193
    int tid = threadIdx.x;
    int w = tid >> 5, lane = tid & 31;
    int row0 = blockIdx.x * 192;
    int head = w / 3;

    ull acc[6][4];
#pragma unroll
    for (int f = 0; f < 6; f++)
#pragma unroll
        for (int j = 0; j < 4; j++) acc[f][j] = 0ull;

    for (int i = tid; i < K * 96; i += 384) Bs[i] = W[i];

    for (int k0 = 0; k0 < K; k0 += KC) {
        __syncthreads();
        for (int i = tid; i < 192 * KC; i += 384) {
            int k = i % KC, r = i / KC;
            int row = row0 + r;
            As[k * 193 + r] = (row < n) ? A[row * K + k0 + k] : 0.f;
        }
        __syncthreads();
#pragma unroll 8
        for (int k = 0; k < KC; k++) {
            const ull* b_ = (const ull*)&Bs[(k0 + k) * 96 + w * 8];
            ull bp0 = b_[0], bp1 = b_[1], bp2 = b_[2], bp3 = b_[3];
            const float* a_ = &As[k * 193 + lane];
#pragma unroll
            for (int f = 0; f < 6; f++) {
                float av = a_[f * 32];
                ull ap = pk2(av, av);
                acc[f][0] = fma2(ap, bp0, acc[f][0]);
                acc[f][1] = fma2(ap, bp1, acc[f][1]);
                acc[f][2] = fma2(ap, bp2, acc[f][2]);
                acc[f][3] = fma2(ap, bp3, acc[f][3]);
            }
        }
    }

    float a_s[8], a_d[8];
#pragma unroll
    for (int j = 0; j < 8; j++) {
        a_s[j] = __ldg(&asrc[w * 8 + j]);
        a_d[j] = __ldg(&adst[w * 8 + j]);
    }
    float* sAl = sm;
    __syncthreads();
    for (int i = tid; i < 192 * 8; i += 384) sAl[i] = 0.f;
    __syncthreads();

#pragma unroll
    for (int f = 0; f < 6; f++) {
        int r = lane + f * 32;
        int row = row0 + r;
        float o0x, o0y, o0z, o0w, o1x, o1y, o1z, o1w;
        upk2(acc[f][0], o0x, o0y);
        upk2(acc[f][1], o0z, o0w);
        upk2(acc[f][2], o1x, o1y);
        upk2(acc[f][3], o1z, o1w);
        if (row < n) {
            float* out = H + row * 96 + w * 8;
            *(float4*)(out)     = make_float4(o0x, o0y, o0z, o0w);
            *(float4*)(out + 4) = make_float4(o1x, o1y, o1z, o1w);
        }
        float sp = o0x * a_s[0] + o0y * a_s[1] + o0z * a_s[2] + o0w * a_s[3]
                 + o1x * a_s[4] + o1y * a_s[5] + o1z * a_s[6] + o1w * a_s[7];
        float dp = o0x * a_d[0] + o0y * a_d[1] + o0z * a_d[2] + o0w * a_d[3]
                 + o1x * a_d[4] + o1y * a_d[5] + o1z * a_d[6] + o1w * a_d[7];
        atomicAdd(&sAl[r * 8 + head], sp);
        atomicAdd(&sAl[r * 8 + 4 + head], dp);
    }
    __syncthreads();
    for (int i = tid; i < 192 * 4; i += 384) {
        int r = i >> 2, hh = i & 3;
        int row = row0 + r;
        if (row < n) {
            AS[row * 4 + hh] = sAl[r * 8 + hh];
            AD[row * 4 + hh] = sAl[r * 8 + 4 + hh];
        }
    }
}

// ================= fused ONLINE softmax + aggregation (warp per dst) =================
__global__ void k_sagg(const int* __restrict__ off, const int* __restrict__ srcs,
                       const float* __restrict__ AS, const float* __restrict__ AD,
                       const float* __restrict__ H, const float* __restrict__ bias,
                       float* __restrict__ OUT, int n) {
    __shared__ int   ssrc[8][32];
    __shared__ float sex[8][128];
    int gtid = blockIdx.x * blockDim.x + threadIdx.x;
    int node = gtid >> 5, lane = gtid & 31;
    int ws = threadIdx.x >> 5;
    if (node >= n) return;
    int beg = __ldg(&off[node]), end = __ldg(&off[node + 1]);
    float4 ad = *(const float4*)(AD + node * 4);

    bool act = lane < 24;
    int head = lane / 6;
    float4 run = make_float4(-INFINITY, -INFINITY, -INFINITY, -INFINITY);
    float4 acc = make_float4(0.f, 0.f, 0.f, 0.f);
    float4 den = make_float4(0.f, 0.f, 0.f, 0.f);

    for (int c0 = beg; c0 < end; c0 += 32) {
        int e = c0 + lane;
        bool valid = e < end;
        int s = 0;
        float4 v = make_float4(-INFINITY, -INFINITY, -INFINITY, -INFINITY);
        if (valid) {
            s = __ldg(&srcs[e]);
            float4 a = *(const float4*)(AS + s * 4);
            float t;
            t = a.x + ad.x; v.x = t > 0.f ? t : 0.2f * t;
            t = a.y + ad.y; v.y = t > 0.f ? t : 0.2f * t;
            t = a.z + ad.z; v.z = t > 0.f ? t : 0.2f * t;
            t = a.w + ad.w; v.w = t > 0.f ? t : 0.2f * t;
        }
        // chunk max across warp
        float4 cm = v;
#pragma unroll
        for (int o = 16; o > 0; o >>= 1) {
            cm.x = fmaxf(cm.x, __shfl_xor_sync(0xffffffffu, cm.x, o));
            cm.y = fmaxf(cm.y, __shfl_xor_sync(0xffffffffu, cm.y, o));
            cm.z = fmaxf(cm.z, __shfl_xor_sync(0xffffffffu, cm.z, o));
            cm.w = fmaxf(cm.w, __shfl_xor_sync(0xffffffffu, cm.w, o));
        }
        float4 nm;
        nm.x = fmaxf(run.x, cm.x); nm.y = fmaxf(run.y, cm.y);
        nm.z = fmaxf(run.z, cm.z); nm.w = fmaxf(run.w, cm.w);
        // rescale factors (run=-INF first chunk -> sc=0, acc/den are 0 anyway)
        float4 sc;
        sc.x = expf(run.x - nm.x); sc.y = expf(run.y - nm.y);
        sc.z = expf(run.z - nm.z); sc.w = expf(run.w - nm.w);
        run = nm;
        den.x *= sc.x; den.y *= sc.y; den.z *= sc.z; den.w *= sc.w;

        float4 ex;
        if (valid) {
            ex.x = expf(v.x - nm.x); ex.y = expf(v.y - nm.y);
            ex.z = expf(v.z - nm.z); ex.w = expf(v.w - nm.w);
            den.x += ex.x; den.y += ex.y; den.z += ex.z; den.w += ex.w;
            ssrc[ws][lane] = s;
            *(float4*)&sex[ws][lane * 4] = ex;
        }
        __syncwarp();
        int cnt = min(32, end - c0);
        if (act) {
            float sh = head == 0 ? sc.x : (head == 1 ? sc.y : (head == 2 ? sc.z : sc.w));
            acc.x *= sh; acc.y *= sh; acc.z *= sh; acc.w *= sh;
#pragma unroll 4
            for (int j = 0; j < cnt; j++) {
                int sj = ssrc[ws][j];
                float wv = sex[ws][j * 4 + head];
                float4 h4 = *(const float4*)(H + sj * 96 + lane * 4);
                acc.x = fmaf(h4.x, wv, acc.x);
                acc.y = fmaf(h4.y, wv, acc.y);
                acc.z = fmaf(h4.z, wv, acc.z);
                acc.w = fmaf(h4.w, wv, acc.w);
            }
        }
        __syncwarp();
    }
#pragma unroll
    for (int o = 16; o > 0; o >>= 1) {
        den.x += __shfl_xor_sync(0xffffffffu, den.x, o);
        den.y += __shfl_xor_sync(0xffffffffu, den.y, o);
        den.z += __shfl_xor_sync(0xffffffffu, den.z, o);
        den.w += __shfl_xor_sync(0xffffffffu, den.w, o);
    }
    if (act) {
        float dh = head == 0 ? den.x : (head == 1 ? den.y : (head == 2 ? den.z : den.w));
        float inv = 1.f / (dh + 1e-16f);
        float4 b4 = *(const float4*)(bias + lane * 4);
        float4 o;
        o.x = acc.x * inv + b4.x;  o.x = o.x > 0.f ? o.x : expm1f(o.x);
        o.y = acc.y * inv + b4.y;  o.y = o.y > 0.f ? o.y : expm1f(o.y);
        o.z = acc.z * inv + b4.z;  o.z = o.z > 0.f ? o.z : expm1f(o.z);
        o.w = acc.w * inv + b4.w;  o.w = o.w > 0.f ? o.w : expm1f(o.w);
        *(float4*)(OUT + node * 96 + lane * 4) = o;
    }
}

// ================= gate MLP: smem weights, 2 nodes per warp =================
__global__ void k_gate(const float* __restrict__ H, const float* __restrict__ gw1,
                       const float* __restrict__ gb1, const float* __restrict__ gw2,
                       const float* __restrict__ gb2, const int* __restrict__ batch,
                       float* __restrict__ GATE, float* __restrict__ GM, int n) {
    __shared__ float sw1[96 * 48];
    __shared__ float sb1[48], sg2[48];
    int tid = threadIdx.x;
    for (int i = tid; i < 96 * 48; i += 256) sw1[i] = gw1[i];
    if (tid < 48) { sb1[tid] = gb1[tid]; sg2[tid] = gw2[tid]; }
    __syncthreads();
    int w = tid >> 5, lane = tid & 31;
    int base = blockIdx.x * 64;
    for (int it = 0; it < 4; it++) {
        int nodeA = base + it * 16 + w * 2;
        int nodeB = nodeA + 1;
        bool vA = nodeA < n, vB = nodeB < n;
        if (!vA) return;
        float a0 = 0.f, a1 = 0.f, b0 = 0.f, b1 = 0.f;
        const float* hA = H + nodeA * 96;
        const float* hB = H + nodeB * 96;
        for (int k = 0; k < 96; k++) {
            float w0 = sw1[k * 48 + lane];
            float hv0 = __ldg(&hA[k]);
            a0 = fmaf(hv0, w0, a0);
            float hv1 = vB ? __ldg(&hB[k]) : 0.f;
            b0 = fmaf(hv1, w0, b0);
            if (lane < 16) {
                float w1 = sw1[k * 48 + 32 + lane];
                a1 = fmaf(hv0, w1, a1);
                b1 = fmaf(hv1, w1, b1);
            }
        }
        float gA = fmaxf(a0 + sb1[lane], 0.f) * sg2[lane];
        float gB = fmaxf(b0 + sb1[lane], 0.f) * sg2[lane];
        if (lane < 16) {
            gA += fmaxf(a1 + sb1[32 + lane], 0.f) * sg2[32 + lane];
            gB += fmaxf(b1 + sb1[32 + lane], 0.f) * sg2[32 + lane];
        }
#pragma unroll
        for (int o = 16; o > 0; o >>= 1) {
            gA += __shfl_xor_sync(0xffffffffu, gA, o);
            gB += __shfl_xor_sync(0xffffffffu, gB, o);
        }
        if (lane == 0) {
            gA += gb2[0];
            GATE[nodeA] = gA;
            atomicMaxF(&GM[batch[nodeA]], gA);
        }
        if (lane == 1 && vB) {
            gB += gb2[0];
            GATE[nodeB] = gB;
            atomicMaxF(&GM[batch[nodeB]], gB);
        }
    }
}

__global__ void k_gate_exp(const float* __restrict__ GATE, const float* __restrict__ GM,
                           const int* __restrict__ batch, float* __restrict__ GE,
                           float* __restrict__ GDEN, int n) {
    __shared__ float sden[GG];
    for (int i = threadIdx.x; i < GG; i += blockDim.x) sden[i] = 0.f;
    __syncthreads();
    int i = blockIdx.x * blockDim.x + threadIdx.x;
    if (i < n) {
        int b = batch[i];
        float m = GM[b];
        if (m == -INFINITY) m = 0.f;
        float e = expf(GATE[i] - m);
        GE[i] = e;
        atomicAdd(&sden[b], e);
    }
    __syncthreads();
    for (int i2 = threadIdx.x; i2 < GG; i2 += blockDim.x)
        if (sden[i2] != 0.f) atomicAdd(&GDEN[i2], sden[i2]);
}

// ================= pooling: 8 blocks per graph -> disjoint partials =================
__global__ void k_pool2(const float* __restrict__ H, const float* __restrict__ GE,
                        const float* __restrict__ GDEN, const int* __restrict__ batch,
                        float* __restrict__ POOL, int n) {
    __shared__ float red[192];
    int g = blockIdx.x;
    int part = blockIdx.y;
    int tid = threadIdx.x;
    int lo = 0, hi = n;
    while (lo < hi) { int mid = (lo + hi) >> 1; if (__ldg(&batch[mid]) < g) lo = mid + 1; else hi = mid; }
    int beg = lo;
    lo = beg; hi = n;
    while (lo < hi) { int mid = (lo + hi) >> 1; if (__ldg(&batch[mid]) < g + 1) lo = mid + 1; else hi = mid; }
    int end = lo;

    float invden = 1.f / (GDEN[g] + 1e-16f);
    int half = tid / 96, c = tid - half * 96;
    float acc = 0.f;
    for (int node = beg + part * 2 + half; node < end; node += 16) {
        float wv = __ldg(&GE[node]) * invden;
        acc = fmaf(__ldg(&H[node * 96 + c]), wv, acc);
    }
    red[tid] = acc;
    __syncthreads();
    if (tid < 96) POOL[(g * 8 + part) * 96 + tid] = red[tid] + red[tid + 96];
}

__global__ void k_final(const float* __restrict__ POOL, const float* __restrict__ fw1,
                        const float* __restrict__ fb1, const float* __restrict__ fw2,
                        const float* __restrict__ fb2, float* __restrict__ out) {
    __shared__ float pr[96];
    __shared__ float hid[96];
    int g = blockIdx.x, j = threadIdx.x;
    float p = 0.f;
#pragma unroll
    for (int q = 0; q < 8; q++) p += POOL[(g * 8 + q) * 96 + j];
    pr[j] = p;
    __syncthreads();
    float a = fb1[j];
#pragma unroll 8
    for (int k = 0; k < 96; k++) a += pr[k] * fw1[k * 96 + j];
    hid[j] = fmaxf(a, 0.f);
    __syncthreads();
    if (j < 3) {
        float o = fb2[j];
        for (int k = 0; k < 96; k++) o += hid[k] * fw2[k * 3 + j];
        out[g * 3 + j] = o;
    }
}

// ================= host =================
extern "C" void kernel_launch(void* const* d_in, const int* in_sizes, int n_in,
                              void* d_out, int out_size) {
    const float* x     = (const float*)d_in[0];
    const int*   ei    = (const int*)d_in[1];
    const int*   batch = (const int*)d_in[2];
    int idx = 3;
    if (n_in > 3 && in_sizes[3] == 1) idx = 4;
    const float* W1  = (const float*)d_in[idx++];
    const float* as1 = (const float*)d_in[idx++];
    const float* ad1 = (const float*)d_in[idx++];
    const float* b1  = (const float*)d_in[idx++];
    const float* W2  = (const float*)d_in[idx++];
    const float* as2 = (const float*)d_in[idx++];
    const float* ad2 = (const float*)d_in[idx++];
    const float* b2  = (const float*)d_in[idx++];
    const float* gw1 = (const float*)d_in[idx++];
    const float* gb1 = (const float*)d_in[idx++];
    const float* gw2 = (const float*)d_in[idx++];
    const float* gb2 = (const float*)d_in[idx++];
    const float* fw1 = (const float*)d_in[idx++];
    const float* fb1 = (const float*)d_in[idx++];
    const float* fw2 = (const float*)d_in[idx++];
    const float* fb2 = (const float*)d_in[idx++];

    int n    = in_sizes[0] / 128;
    int eraw = in_sizes[1] / 2;
    int etot = eraw + n;

    float *h, *o, *as_, *ad_, *gate, *ge, *gm, *gden, *pool;
    int *deg, *part, *bsum, *off, *srcs;
    cudaGetSymbolAddress((void**)&h,    d_h);
    cudaGetSymbolAddress((void**)&o,    d_o);
    cudaGetSymbolAddress((void**)&as_,  d_as);
    cudaGetSymbolAddress((void**)&ad_,  d_ad);
    cudaGetSymbolAddress((void**)&gate, d_gate);
    cudaGetSymbolAddress((void**)&ge,   d_ge);
    cudaGetSymbolAddress((void**)&gm,   d_gm);
    cudaGetSymbolAddress((void**)&gden, d_gden);
    cudaGetSymbolAddress((void**)&pool, d_pool);
    cudaGetSymbolAddress((void**)&deg,  d_deg);
    cudaGetSymbolAddress((void**)&part, d_part);
    cudaGetSymbolAddress((void**)&bsum, d_bsum);
    cudaGetSymbolAddress((void**)&off,  d_off);
    cudaGetSymbolAddress((void**)&srcs, d_srcs);

    int smem1 = (128 * 96 + 64 * 193) * 4;
    int smem2 = (96 * 96 + 96 * 193) * 4;
    cudaFuncSetAttribute(k_gemm2<128, 64>, cudaFuncAttributeMaxDynamicSharedMemorySize, smem1);
    cudaFuncSetAttribute(k_gemm2<96, 96>,  cudaFuncAttributeMaxDynamicSharedMemorySize, smem2);

    int gEdge  = (etot + 255) / 256;
    int gWarp  = (n * 32 + 255) / 256;
    int gGemm  = (n + 191) / 192;
    int gNode  = (n + 255) / 256;
    int gScan  = (n + 1023) / 1024;

    // ---- CSR build ----
    cudaMemsetAsync(deg, 0, n * sizeof(int));
    k_hist<<<gEdge, 256>>>(ei, deg, etot, eraw);
    k_scanA<<<gScan, 1024>>>(deg, part, bsum, n);
    k_scanB<<<1, 64>>>(bsum, gScan);
    k_scanC<<<gScan, 1024>>>(part, bsum, off, deg, gm, gden, n, etot);
    k_scatter<<<gEdge, 256>>>(ei, deg, srcs, etot, eraw);

    // ---- layer 1 ----
    k_gemm2<128, 64><<<gGemm, 384, smem1>>>(x, W1, as1, ad1, h, as_, ad_, n);
    k_sagg<<<gWarp, 256>>>(off, srcs, as_, ad_, h, b1, o, n);

    // ---- layer 2 ----
    k_gemm2<96, 96><<<gGemm, 384, smem2>>>(o, W2, as2, ad2, h, as_, ad_, n);
    k_sagg<<<gWarp, 256>>>(off, srcs, as_, ad_, h, b2, o, n);

    // ---- global attention pool + final MLP ----
    k_gate<<<(n + 63) / 64, 256>>>(o, gw1, gb1, gw2, gb2, batch, gate, gm, n);
    k_gate_exp<<<gNode, 256>>>(gate, gm, batch, ge, gden, n);
    k_pool2<<<dim3(GG, 8), 192>>>(o, ge, gden, batch, pool, n);
    k_final<<<GG, 96>>>(pool, fw1, fb1, fw2, fb2, (float*)d_out);
}

// round 8
// speedup vs baseline: 1.0330x; 1.0330x over previous
#include <cuda_runtime.h>
#include <math.h>

#define NN 50000
#define EE 800000
#define ETOT (EE + NN)
#define GG 64

// ---------------- scratch ----------------
__device__ float d_h[NN * 96];
__device__ float d_o[NN * 96];
__device__ float d_as[NN * 4];
__device__ float d_ad[NN * 4];
__device__ int   d_deg[NN];
__device__ int   d_part[NN];
__device__ int   d_bsum[64];
__device__ int   d_off[NN + 1];
__device__ int   d_srcs[ETOT];
__device__ float d_gate[NN];
__device__ float d_ge[NN];
__device__ float d_gm[GG];
__device__ float d_gden[GG];
__device__ float d_pool[GG * 8 * 96];

__device__ __forceinline__ void atomicMaxF(float* a, float v) {
    if (v >= 0.f) atomicMax((int*)a, __float_as_int(v));
    else          atomicMin((unsigned int*)a, __float_as_uint(v));
}

typedef unsigned long long ull;
__device__ __forceinline__ ull pk2(float x, float y) {
    ull r;
    asm("mov.b64 %0, {%1, %2};" : "=l"(r) : "f"(x), "f"(y));
    return r;
}
__device__ __forceinline__ ull fma2(ull a, ull b, ull c) {
    ull d;
    asm("fma.rn.f32x2 %0, %1, %2, %3;" : "=l"(d) : "l"(a), "l"(b), "l"(c));
    return d;
}
__device__ __forceinline__ void upk2(ull v, float& x, float& y) {
    asm("mov.b64 {%0, %1}, %2;" : "=f"(x), "=f"(y) : "l"(v));
}

// ================= CSR build =================
__global__ void k_hist(const int* __restrict__ ei, int* __restrict__ deg, int etot, int eraw) {
    int e = blockIdx.x * blockDim.x + threadIdx.x;
    if (e >= etot) return;
    int d = (e < eraw) ? __ldg(&ei[eraw + e]) : e - eraw;
    atomicAdd(&deg[d], 1);
}

__global__ void k_scanA(const int* __restrict__ deg, int* __restrict__ part,
                        int* __restrict__ bsum, int n) {
    __shared__ int wsum[32];
    int t = threadIdx.x;
    int i = blockIdx.x * 1024 + t;
    int v = (i < n) ? deg[i] : 0;
    int lane = t & 31, w = t >> 5;
    int x = v;
#pragma unroll
    for (int o = 1; o < 32; o <<= 1) {
        int y = __shfl_up_sync(0xffffffffu, x, o);
        if (lane >= o) x += y;
    }
    if (lane == 31) wsum[w] = x;
    __syncthreads();
    if (w == 0) {
        int s = wsum[lane];
#pragma unroll
        for (int o = 1; o < 32; o <<= 1) {
            int y = __shfl_up_sync(0xffffffffu, s, o);
            if (lane >= o) s += y;
        }
        wsum[lane] = s;
    }
    __syncthreads();
    int woff = (w > 0) ? wsum[w - 1] : 0;
    if (i < n) part[i] = x - v + woff;
    if (t == 0) bsum[blockIdx.x] = wsum[31];
}

__global__ void k_scanB(int* __restrict__ bsum, int nb) {
    __shared__ int w0tot;
    int t = threadIdx.x;
    int lane = t & 31, w = t >> 5;
    int v = (t < nb) ? bsum[t] : 0;
    int x = v;
#pragma unroll
    for (int o = 1; o < 32; o <<= 1) {
        int y = __shfl_up_sync(0xffffffffu, x, o);
        if (lane >= o) x += y;
    }
    if (w == 0 && lane == 31) w0tot = x;
    __syncthreads();
    if (w == 1) x += w0tot;
    if (t < nb) bsum[t] = x - v;
}

__global__ void k_scanC(const int* __restrict__ part, const int* __restrict__ bsum,
                        int* __restrict__ off, int* __restrict__ cur,
                        float* __restrict__ GM, float* __restrict__ GDEN,
                        int n, int etot) {
    int i = blockIdx.x * 1024 + threadIdx.x;
    if (i < n) {
        int v = part[i] + bsum[blockIdx.x];
        off[i] = v;
        cur[i] = v;
    }
    if (i == 0) off[n] = etot;
    if (blockIdx.x == 0 && threadIdx.x < GG) {
        GM[threadIdx.x] = -INFINITY;
        GDEN[threadIdx.x] = 0.f;
    }
}

__global__ void k_scatter(const int* __restrict__ ei, int* __restrict__ cur,
                          int* __restrict__ srcs, int etot, int eraw) {
    int e = blockIdx.x * blockDim.x + threadIdx.x;
    if (e >= etot) return;
    int s, d;
    if (e < eraw) { s = __ldg(&ei[e]); d = __ldg(&ei[eraw + e]); }
    else          { s = d = e - eraw; }
    int pos = atomicAdd(&cur[d], 1);
    srcs[pos] = s;
}

// ================= GEMM + fused alpha epilogue =================
template<int K, int KC>
__global__ void __launch_bounds__(384, 2) k_gemm2(const float* __restrict__ A,
                                                  const float* __restrict__ W,
                                                  const float* __restrict__ asrc,
                                                  const float* __restrict__ adst,
                                                  float* __restrict__ H,
                                                  float* __restrict__ AS,
                                                  float* __restrict__ AD, int n) {
    extern __shared__ float sm[];
    float* Bs = sm;              // K*96 (full weights, global-k)
    float* As = sm + K * 96;     // KC*193
    int tid = threadIdx.x;
    int w = tid >> 5, lane = tid & 31;
    int row0 = blockIdx.x * 192;
    int head = w / 3;

    ull acc[6][4];
#pragma unroll
    for (int f = 0; f < 6; f++)
#pragma unroll
        for (int j = 0; j < 4; j++) acc[f][j] = 0ull;

    for (int i = tid; i < K * 96; i += 384) Bs[i] = W[i];

    for (int k0 = 0; k0 < K; k0 += KC) {
        __syncthreads();
        for (int i = tid; i < 192 * KC; i += 384) {
            int k = i % KC, r = i / KC;
            int row = row0 + r;
            As[k * 193 + r] = (row < n) ? A[row * K + k0 + k] : 0.f;
        }
        __syncthreads();
#pragma unroll 8
        for (int k = 0; k < KC; k++) {
            const ull* b_ = (const ull*)&Bs[(k0 + k) * 96 + w * 8];
            ull bp0 = b_[0], bp1 = b_[1], bp2 = b_[2], bp3 = b_[3];
            const float* a_ = &As[k * 193 + lane];
#pragma unroll
            for (int f = 0; f < 6; f++) {
                float av = a_[f * 32];
                ull ap = pk2(av, av);
                acc[f][0] = fma2(ap, bp0, acc[f][0]);
                acc[f][1] = fma2(ap, bp1, acc[f][1]);
                acc[f][2] = fma2(ap, bp2, acc[f][2]);
                acc[f][3] = fma2(ap, bp3, acc[f][3]);
            }
        }
    }

    float a_s[8], a_d[8];
#pragma unroll
    for (int j = 0; j < 8; j++) {
        a_s[j] = __ldg(&asrc[w * 8 + j]);
        a_d[j] = __ldg(&adst[w * 8 + j]);
    }
    float* sAl = sm;
    __syncthreads();
    for (int i = tid; i < 192 * 8; i += 384) sAl[i] = 0.f;
    __syncthreads();

#pragma unroll
    for (int f = 0; f < 6; f++) {
        int r = lane + f * 32;
        int row = row0 + r;
        float o0x, o0y, o0z, o0w, o1x, o1y, o1z, o1w;
        upk2(acc[f][0], o0x, o0y);
        upk2(acc[f][1], o0z, o0w);
        upk2(acc[f][2], o1x, o1y);
        upk2(acc[f][3], o1z, o1w);
        if (row < n) {
            float* out = H + row * 96 + w * 8;
            *(float4*)(out)     = make_float4(o0x, o0y, o0z, o0w);
            *(float4*)(out + 4) = make_float4(o1x, o1y, o1z, o1w);
        }
        float sp = o0x * a_s[0] + o0y * a_s[1] + o0z * a_s[2] + o0w * a_s[3]
                 + o1x * a_s[4] + o1y * a_s[5] + o1z * a_s[6] + o1w * a_s[7];
        float dp = o0x * a_d[0] + o0y * a_d[1] + o0z * a_d[2] + o0w * a_d[3]
                 + o1x * a_d[4] + o1y * a_d[5] + o1z * a_d[6] + o1w * a_d[7];
        atomicAdd(&sAl[r * 8 + head], sp);
        atomicAdd(&sAl[r * 8 + 4 + head], dp);
    }
    __syncthreads();
    for (int i = tid; i < 192 * 4; i += 384) {
        int r = i >> 2, hh = i & 3;
        int row = row0 + r;
        if (row < n) {
            AS[row * 4 + hh] = sAl[r * 8 + hh];
            AD[row * 4 + hh] = sAl[r * 8 + 4 + hh];
        }
    }
}

// ================= fused softmax + aggregation (warp per dst, smem-cached logits) =================
#define DCAP 128
__global__ void k_sagg(const int* __restrict__ off, const int* __restrict__ srcs,
                       const float* __restrict__ AS, const float* __restrict__ AD,
                       const float* __restrict__ H, const float* __restrict__ bias,
                       float* __restrict__ OUT, int n) {
    __shared__ int    ssrc[8][DCAP];
    __shared__ float4 slog[8][DCAP];
    int gtid = blockIdx.x * blockDim.x + threadIdx.x;
    int node = gtid >> 5, lane = gtid & 31;
    int ws = threadIdx.x >> 5;
    if (node >= n) return;
    int beg = __ldg(&off[node]), end = __ldg(&off[node + 1]);
    int deg = end - beg;
    float4 ad = *(const float4*)(AD + node * 4);

    bool act = lane < 24;
    int head = lane / 6;
    float4 acc = make_float4(0.f, 0.f, 0.f, 0.f);
    float4 den = make_float4(0.f, 0.f, 0.f, 0.f);
    float4 mx = make_float4(-INFINITY, -INFINITY, -INFINITY, -INFINITY);

    if (deg <= DCAP) {
        // ---- pass 1: gather once, cache src + logits in smem, compute max ----
        for (int j = lane; j < deg; j += 32) {
            int s = __ldg(&srcs[beg + j]);
            float4 a = *(const float4*)(AS + s * 4);
            float t; float4 v;
            t = a.x + ad.x; v.x = t > 0.f ? t : 0.2f * t; mx.x = fmaxf(mx.x, v.x);
            t = a.y + ad.y; v.y = t > 0.f ? t : 0.2f * t; mx.y = fmaxf(mx.y, v.y);
            t = a.z + ad.z; v.z = t > 0.f ? t : 0.2f * t; mx.z = fmaxf(mx.z, v.z);
            t = a.w + ad.w; v.w = t > 0.f ? t : 0.2f * t; mx.w = fmaxf(mx.w, v.w);
            ssrc[ws][j] = s;
            slog[ws][j] = v;
        }
#pragma unroll
        for (int o = 16; o > 0; o >>= 1) {
            mx.x = fmaxf(mx.x, __shfl_xor_sync(0xffffffffu, mx.x, o));
            mx.y = fmaxf(mx.y, __shfl_xor_sync(0xffffffffu, mx.y, o));
            mx.z = fmaxf(mx.z, __shfl_xor_sync(0xffffffffu, mx.z, o));
            mx.w = fmaxf(mx.w, __shfl_xor_sync(0xffffffffu, mx.w, o));
        }
        __syncwarp();
        // ---- pass 2a: exp from smem, denominator ----
        for (int j = lane; j < deg; j += 32) {
            float4 v = slog[ws][j];
            float4 ex;
            ex.x = expf(v.x - mx.x); ex.y = expf(v.y - mx.y);
            ex.z = expf(v.z - mx.z); ex.w = expf(v.w - mx.w);
            slog[ws][j] = ex;
            den.x += ex.x; den.y += ex.y; den.z += ex.z; den.w += ex.w;
        }
        __syncwarp();
        // ---- pass 2b: straight aggregation over all edges ----
        if (act) {
            const float* sexf = (const float*)&slog[ws][0];
#pragma unroll 4
            for (int j = 0; j < deg; j++) {
                int s = ssrc[ws][j];
                float wv = sexf[j * 4 + head];
                float4 h4 = *(const float4*)(H + s * 96 + lane * 4);
                acc.x = fmaf(h4.x, wv, acc.x);
                acc.y = fmaf(h4.y, wv, acc.y);
                acc.z = fmaf(h4.z, wv, acc.z);
                acc.w = fmaf(h4.w, wv, acc.w);
            }
        }
    } else {
        // ---- rare fallback: two-pass chunked recompute ----
        for (int e = beg + lane; e < end; e += 32) {
            int s = __ldg(&srcs[e]);
            float4 a = *(const float4*)(AS + s * 4);
            float t;
            t = a.x + ad.x; t = t > 0.f ? t : 0.2f * t; mx.x = fmaxf(mx.x, t);
            t = a.y + ad.y; t = t > 0.f ? t : 0.2f * t; mx.y = fmaxf(mx.y, t);
            t = a.z + ad.z; t = t > 0.f ? t : 0.2f * t; mx.z = fmaxf(mx.z, t);
            t = a.w + ad.w; t = t > 0.f ? t : 0.2f * t; mx.w = fmaxf(mx.w, t);
        }
#pragma unroll
        for (int o = 16; o > 0; o >>= 1) {
            mx.x = fmaxf(mx.x, __shfl_xor_sync(0xffffffffu, mx.x, o));
            mx.y = fmaxf(mx.y, __shfl_xor_sync(0xffffffffu, mx.y, o));
            mx.z = fmaxf(mx.z, __shfl_xor_sync(0xffffffffu, mx.z, o));
            mx.w = fmaxf(mx.w, __shfl_xor_sync(0xffffffffu, mx.w, o));
        }
        for (int c0 = beg; c0 < end; c0 += 32) {
            int e = c0 + lane;
            if (e < end) {
                int s = __ldg(&srcs[e]);
                float4 a = *(const float4*)(AS + s * 4);
                float t; float4 ex;
                t = a.x + ad.x; t = t > 0.f ? t : 0.2f * t; ex.x = expf(t - mx.x);
                t = a.y + ad.y; t = t > 0.f ? t : 0.2f * t; ex.y = expf(t - mx.y);
                t = a.z + ad.z; t = t > 0.f ? t : 0.2f * t; ex.z = expf(t - mx.z);
                t = a.w + ad.w; t = t > 0.f ? t : 0.2f * t; ex.w = expf(t - mx.w);
                den.x += ex.x; den.y += ex.y; den.z += ex.z; den.w += ex.w;
                ssrc[ws][lane] = __ldg(&srcs[e]);
                slog[ws][lane] = ex;
            }
            __syncwarp();
            int cnt = min(32, end - c0);
            if (act) {
                const float* sexf = (const float*)&slog[ws][0];
                for (int j = 0; j < cnt; j++) {
                    int s = ssrc[ws][j];
                    float wv = sexf[j * 4 + head];
                    float4 h4 = *(const float4*)(H + s * 96 + lane * 4);
                    acc.x = fmaf(h4.x, wv, acc.x);
                    acc.y = fmaf(h4.y, wv, acc.y);
                    acc.z = fmaf(h4.z, wv, acc.z);
                    acc.w = fmaf(h4.w, wv, acc.w);
                }
            }
            __syncwarp();
        }
    }

#pragma unroll
    for (int o = 16; o > 0; o >>= 1) {
        den.x += __shfl_xor_sync(0xffffffffu, den.x, o);
        den.y += __shfl_xor_sync(0xffffffffu, den.y, o);
        den.z += __shfl_xor_sync(0xffffffffu, den.z, o);
        den.w += __shfl_xor_sync(0xffffffffu, den.w, o);
    }
    if (act) {
        float dh = head == 0 ? den.x : (head == 1 ? den.y : (head == 2 ? den.z : den.w));
        float inv = 1.f / (dh + 1e-16f);
        float4 b4 = *(const float4*)(bias + lane * 4);
        float4 o;
        o.x = acc.x * inv + b4.x;  o.x = o.x > 0.f ? o.x : expm1f(o.x);
        o.y = acc.y * inv + b4.y;  o.y = o.y > 0.f ? o.y : expm1f(o.y);
        o.z = acc.z * inv + b4.z;  o.z = o.z > 0.f ? o.z : expm1f(o.z);
        o.w = acc.w * inv + b4.w;  o.w = o.w > 0.f ? o.w : expm1f(o.w);
        *(float4*)(OUT + node * 96 + lane * 4) = o;
    }
}

// ================= gate MLP: smem weights, 2 nodes per warp =================
__global__ void k_gate(const float* __restrict__ H, const float* __restrict__ gw1,
                       const float* __restrict__ gb1, const float* __restrict__ gw2,
                       const float* __restrict__ gb2, const int* __restrict__ batch,
                       float* __restrict__ GATE, float* __restrict__ GM, int n) {
    __shared__ float sw1[96 * 48];
    __shared__ float sb1[48], sg2[48];
    int tid = threadIdx.x;
    for (int i = tid; i < 96 * 48; i += 256) sw1[i] = gw1[i];
    if (tid < 48) { sb1[tid] = gb1[tid]; sg2[tid] = gw2[tid]; }
    __syncthreads();
    int w = tid >> 5, lane = tid & 31;
    int base = blockIdx.x * 64;
    for (int it = 0; it < 4; it++) {
        int nodeA = base + it * 16 + w * 2;
        int nodeB = nodeA + 1;
        bool vA = nodeA < n, vB = nodeB < n;
        if (!vA) return;
        float a0 = 0.f, a1 = 0.f, b0 = 0.f, b1 = 0.f;
        const float* hA = H + nodeA * 96;
        const float* hB = H + nodeB * 96;
        for (int k = 0; k < 96; k++) {
            float w0 = sw1[k * 48 + lane];
            float hv0 = __ldg(&hA[k]);
            a0 = fmaf(hv0, w0, a0);
            float hv1 = vB ? __ldg(&hB[k]) : 0.f;
            b0 = fmaf(hv1, w0, b0);
            if (lane < 16) {
                float w1 = sw1[k * 48 + 32 + lane];
                a1 = fmaf(hv0, w1, a1);
                b1 = fmaf(hv1, w1, b1);
            }
        }
        float gA = fmaxf(a0 + sb1[lane], 0.f) * sg2[lane];
        float gB = fmaxf(b0 + sb1[lane], 0.f) * sg2[lane];
        if (lane < 16) {
            gA += fmaxf(a1 + sb1[32 + lane], 0.f) * sg2[32 + lane];
            gB += fmaxf(b1 + sb1[32 + lane], 0.f) * sg2[32 + lane];
        }
#pragma unroll
        for (int o = 16; o > 0; o >>= 1) {
            gA += __shfl_xor_sync(0xffffffffu, gA, o);
            gB += __shfl_xor_sync(0xffffffffu, gB, o);
        }
        if (lane == 0) {
            gA += gb2[0];
            GATE[nodeA] = gA;
            atomicMaxF(&GM[batch[nodeA]], gA);
        }
        if (lane == 1 && vB) {
            gB += gb2[0];
            GATE[nodeB] = gB;
            atomicMaxF(&GM[batch[nodeB]], gB);
        }
    }
}

__global__ void k_gate_exp(const float* __restrict__ GATE, const float* __restrict__ GM,
                           const int* __restrict__ batch, float* __restrict__ GE,
                           float* __restrict__ GDEN, int n) {
    __shared__ float sden[GG];
    for (int i = threadIdx.x; i < GG; i += blockDim.x) sden[i] = 0.f;
    __syncthreads();
    int i = blockIdx.x * blockDim.x + threadIdx.x;
    if (i < n) {
        int b = batch[i];
        float m = GM[b];
        if (m == -INFINITY) m = 0.f;
        float e = expf(GATE[i] - m);
        GE[i] = e;
        atomicAdd(&sden[b], e);
    }
    __syncthreads();
    for (int i2 = threadIdx.x; i2 < GG; i2 += blockDim.x)
        if (sden[i2] != 0.f) atomicAdd(&GDEN[i2], sden[i2]);
}

// ================= pooling: 8 blocks per graph -> disjoint partials =================
__global__ void k_pool2(const float* __restrict__ H, const float* __restrict__ GE,
                        const float* __restrict__ GDEN, const int* __restrict__ batch,
                        float* __restrict__ POOL, int n) {
    __shared__ float red[192];
    int g = blockIdx.x;
    int part = blockIdx.y;
    int tid = threadIdx.x;
    int lo = 0, hi = n;
    while (lo < hi) { int mid = (lo + hi) >> 1; if (__ldg(&batch[mid]) < g) lo = mid + 1; else hi = mid; }
    int beg = lo;
    lo = beg; hi = n;
    while (lo < hi) { int mid = (lo + hi) >> 1; if (__ldg(&batch[mid]) < g + 1) lo = mid + 1; else hi = mid; }
    int end = lo;

    float invden = 1.f / (GDEN[g] + 1e-16f);
    int half = tid / 96, c = tid - half * 96;
    float acc = 0.f;
    for (int node = beg + part * 2 + half; node < end; node += 16) {
        float wv = __ldg(&GE[node]) * invden;
        acc = fmaf(__ldg(&H[node * 96 + c]), wv, acc);
    }
    red[tid] = acc;
    __syncthreads();
    if (tid < 96) POOL[(g * 8 + part) * 96 + tid] = red[tid] + red[tid + 96];
}

__global__ void k_final(const float* __restrict__ POOL, const float* __restrict__ fw1,
                        const float* __restrict__ fb1, const float* __restrict__ fw2,
                        const float* __restrict__ fb2, float* __restrict__ out) {
    __shared__ float pr[96];
    __shared__ float hid[96];
    int g = blockIdx.x, j = threadIdx.x;
    float p = 0.f;
#pragma unroll
    for (int q = 0; q < 8; q++) p += POOL[(g * 8 + q) * 96 + j];
    pr[j] = p;
    __syncthreads();
    float a = fb1[j];
#pragma unroll 8
    for (int k = 0; k < 96; k++) a += pr[k] * fw1[k * 96 + j];
    hid[j] = fmaxf(a, 0.f);
    __syncthreads();
    if (j < 3) {
        float o = fb2[j];
        for (int k = 0; k < 96; k++) o += hid[k] * fw2[k * 3 + j];
        out[g * 3 + j] = o;
    }
}

// ================= host =================
extern "C" void kernel_launch(void* const* d_in, const int* in_sizes, int n_in,
                              void* d_out, int out_size) {
    const float* x     = (const float*)d_in[0];
    const int*   ei    = (const int*)d_in[1];
    const int*   batch = (const int*)d_in[2];
    int idx = 3;
    if (n_in > 3 && in_sizes[3] == 1) idx = 4;
    const float* W1  = (const float*)d_in[idx++];
    const float* as1 = (const float*)d_in[idx++];
    const float* ad1 = (const float*)d_in[idx++];
    const float* b1  = (const float*)d_in[idx++];
    const float* W2  = (const float*)d_in[idx++];
    const float* as2 = (const float*)d_in[idx++];
    const float* ad2 = (const float*)d_in[idx++];
    const float* b2  = (const float*)d_in[idx++];
    const float* gw1 = (const float*)d_in[idx++];
    const float* gb1 = (const float*)d_in[idx++];
    const float* gw2 = (const float*)d_in[idx++];
    const float* gb2 = (const float*)d_in[idx++];
    const float* fw1 = (const float*)d_in[idx++];
    const float* fb1 = (const float*)d_in[idx++];
    const float* fw2 = (const float*)d_in[idx++];
    const float* fb2 = (const float*)d_in[idx++];

    int n    = in_sizes[0] / 128;
    int eraw = in_sizes[1] / 2;
    int etot = eraw + n;

    float *h, *o, *as_, *ad_, *gate, *ge, *gm, *gden, *pool;
    int *deg, *part, *bsum, *off, *srcs;
    cudaGetSymbolAddress((void**)&h,    d_h);
    cudaGetSymbolAddress((void**)&o,    d_o);
    cudaGetSymbolAddress((void**)&as_,  d_as);
    cudaGetSymbolAddress((void**)&ad_,  d_ad);
    cudaGetSymbolAddress((void**)&gate, d_gate);
    cudaGetSymbolAddress((void**)&ge,   d_ge);
    cudaGetSymbolAddress((void**)&gm,   d_gm);
    cudaGetSymbolAddress((void**)&gden, d_gden);
    cudaGetSymbolAddress((void**)&pool, d_pool);
    cudaGetSymbolAddress((void**)&deg,  d_deg);
    cudaGetSymbolAddress((void**)&part, d_part);
    cudaGetSymbolAddress((void**)&bsum, d_bsum);
    cudaGetSymbolAddress((void**)&off,  d_off);
    cudaGetSymbolAddress((void**)&srcs, d_srcs);

    int smem1 = (128 * 96 + 64 * 193) * 4;
    int smem2 = (96 * 96 + 96 * 193) * 4;
    cudaFuncSetAttribute(k_gemm2<128, 64>, cudaFuncAttributeMaxDynamicSharedMemorySize, smem1);
    cudaFuncSetAttribute(k_gemm2<96, 96>,  cudaFuncAttributeMaxDynamicSharedMemorySize, smem2);

    int gEdge  = (etot + 255) / 256;
    int gWarp  = (n * 32 + 255) / 256;
    int gGemm  = (n + 191) / 192;
    int gNode  = (n + 255) / 256;
    int gScan  = (n + 1023) / 1024;

    // ---- CSR build ----
    cudaMemsetAsync(deg, 0, n * sizeof(int));
    k_hist<<<gEdge, 256>>>(ei, deg, etot, eraw);
    k_scanA<<<gScan, 1024>>>(deg, part, bsum, n);
    k_scanB<<<1, 64>>>(bsum, gScan);
    k_scanC<<<gScan, 1024>>>(part, bsum, off, deg, gm, gden, n, etot);
    k_scatter<<<gEdge, 256>>>(ei, deg, srcs, etot, eraw);

    // ---- layer 1 ----
    k_gemm2<128, 64><<<gGemm, 384, smem1>>>(x, W1, as1, ad1, h, as_, ad_, n);
    k_sagg<<<gWarp, 256>>>(off, srcs, as_, ad_, h, b1, o, n);

    // ---- layer 2 ----
    k_gemm2<96, 96><<<gGemm, 384, smem2>>>(o, W2, as2, ad2, h, as_, ad_, n);
    k_sagg<<<gWarp, 256>>>(off, srcs, as_, ad_, h, b2, o, n);

    // ---- global attention pool + final MLP ----
    k_gate<<<(n + 63) / 64, 256>>>(o, gw1, gb1, gw2, gb2, batch, gate, gm, n);
    k_gate_exp<<<gNode, 256>>>(gate, gm, batch, ge, gden, n);
    k_pool2<<<dim3(GG, 8), 192>>>(o, ge, gden, batch, pool, n);
    k_final<<<GG, 96>>>(pool, fw1, fb1, fw2, fb2, (float*)d_out);
}

// round 9
// speedup vs baseline: 1.1126x; 1.0771x over previous
#include <cuda_runtime.h>
#include <cuda_fp16.h>
#include <math.h>

#define NN 50000
#define EE 800000
#define ETOT (EE + NN)
#define GG 64

// ---------------- scratch ----------------
__device__ __half2 d_h2[NN * 48];   // fp16 message matrix (H), 48 half2 per row
__device__ float d_o[NN * 96];
__device__ float d_as[NN * 4];
__device__ float d_ad[NN * 4];
__device__ int   d_deg[NN];
__device__ int   d_part[NN];
__device__ int   d_bsum[64];
__device__ int   d_off[NN + 1];
__device__ int   d_srcs[ETOT];
__device__ float d_gate[NN];
__device__ float d_ge[NN];
__device__ float d_gm[GG];
__device__ float d_gden[GG];
__device__ float d_pool[GG * 8 * 96];

__device__ __forceinline__ void atomicMaxF(float* a, float v) {
    if (v >= 0.f) atomicMax((int*)a, __float_as_int(v));
    else          atomicMin((unsigned int*)a, __float_as_uint(v));
}

typedef unsigned long long ull;
__device__ __forceinline__ ull pk2(float x, float y) {
    ull r;
    asm("mov.b64 %0, {%1, %2};" : "=l"(r) : "f"(x), "f"(y));
    return r;
}
__device__ __forceinline__ ull fma2(ull a, ull b, ull c) {
    ull d;
    asm("fma.rn.f32x2 %0, %1, %2, %3;" : "=l"(d) : "l"(a), "l"(b), "l"(c));
    return d;
}
__device__ __forceinline__ void upk2(ull v, float& x, float& y) {
    asm("mov.b64 {%0, %1}, %2;" : "=f"(x), "=f"(y) : "l"(v));
}

// ================= CSR build =================
__global__ void k_hist(const int* __restrict__ ei, int* __restrict__ deg, int etot, int eraw) {
    int e = blockIdx.x * blockDim.x + threadIdx.x;
    if (e >= etot) return;
    int d = (e < eraw) ? __ldg(&ei[eraw + e]) : e - eraw;
    atomicAdd(&deg[d], 1);
}

__global__ void k_scanA(const int* __restrict__ deg, int* __restrict__ part,
                        int* __restrict__ bsum, int n) {
    __shared__ int wsum[32];
    int t = threadIdx.x;
    int i = blockIdx.x * 1024 + t;
    int v = (i < n) ? deg[i] : 0;
    int lane = t & 31, w = t >> 5;
    int x = v;
#pragma unroll
    for (int o = 1; o < 32; o <<= 1) {
        int y = __shfl_up_sync(0xffffffffu, x, o);
        if (lane >= o) x += y;
    }
    if (lane == 31) wsum[w] = x;
    __syncthreads();
    if (w == 0) {
        int s = wsum[lane];
#pragma unroll
        for (int o = 1; o < 32; o <<= 1) {
            int y = __shfl_up_sync(0xffffffffu, s, o);
            if (lane >= o) s += y;
        }
        wsum[lane] = s;
    }
    __syncthreads();
    int woff = (w > 0) ? wsum[w - 1] : 0;
    if (i < n) part[i] = x - v + woff;
    if (t == 0) bsum[blockIdx.x] = wsum[31];
}

__global__ void k_scanB(int* __restrict__ bsum, int nb) {
    __shared__ int w0tot;
    int t = threadIdx.x;
    int lane = t & 31, w = t >> 5;
    int v = (t < nb) ? bsum[t] : 0;
    int x = v;
#pragma unroll
    for (int o = 1; o < 32; o <<= 1) {
        int y = __shfl_up_sync(0xffffffffu, x, o);
        if (lane >= o) x += y;
    }
    if (w == 0 && lane == 31) w0tot = x;
    __syncthreads();
    if (w == 1) x += w0tot;
    if (t < nb) bsum[t] = x - v;
}

__global__ void k_scanC(const int* __restrict__ part, const int* __restrict__ bsum,
                        int* __restrict__ off, int* __restrict__ cur,
                        float* __restrict__ GM, float* __restrict__ GDEN,
                        int n, int etot) {
    int i = blockIdx.x * 1024 + threadIdx.x;
    if (i < n) {
        int v = part[i] + bsum[blockIdx.x];
        off[i] = v;
        cur[i] = v;
    }
    if (i == 0) off[n] = etot;
    if (blockIdx.x == 0 && threadIdx.x < GG) {
        GM[threadIdx.x] = -INFINITY;
        GDEN[threadIdx.x] = 0.f;
    }
}

__global__ void k_scatter(const int* __restrict__ ei, int* __restrict__ cur,
                          int* __restrict__ srcs, int etot, int eraw) {
    int e = blockIdx.x * blockDim.x + threadIdx.x;
    if (e >= etot) return;
    int s, d;
    if (e < eraw) { s = __ldg(&ei[e]); d = __ldg(&ei[eraw + e]); }
    else          { s = d = e - eraw; }
    int pos = atomicAdd(&cur[d], 1);
    srcs[pos] = s;
}

// ================= GEMM + fused alpha epilogue (H stored fp16) =================
template<int K, int KC>
__global__ void __launch_bounds__(384, 2) k_gemm2(const float* __restrict__ A,
                                                  const float* __restrict__ W,
                                                  const float* __restrict__ asrc,
                                                  const float* __restrict__ adst,
                                                  __half2* __restrict__ H2,
                                                  float* __restrict__ AS,
                                                  float* __restrict__ AD, int n) {
    extern __shared__ float sm[];
    float* Bs = sm;              // K*96 (full weights, global-k)
    float* As = sm + K * 96;     // KC*193
    int tid = threadIdx.x;
    int w = tid >> 5, lane = tid & 31;
    int row0 = blockIdx.x * 192;
    int head = w / 3;

    ull acc[6][4];
#pragma unroll
    for (int f = 0; f < 6; f++)
#pragma unroll
        for (int j = 0; j < 4; j++) acc[f][j] = 0ull;

    for (int i = tid; i < K * 96; i += 384) Bs[i] = W[i];

    for (int k0 = 0; k0 < K; k0 += KC) {
        __syncthreads();
        for (int i = tid; i < 192 * KC; i += 384) {
            int k = i % KC, r = i / KC;
            int row = row0 + r;
            As[k * 193 + r] = (row < n) ? A[row * K + k0 + k] : 0.f;
        }
        __syncthreads();
#pragma unroll 8
        for (int k = 0; k < KC; k++) {
            const ull* b_ = (const ull*)&Bs[(k0 + k) * 96 + w * 8];
            ull bp0 = b_[0], bp1 = b_[1], bp2 = b_[2], bp3 = b_[3];
            const float* a_ = &As[k * 193 + lane];
#pragma unroll
            for (int f = 0; f < 6; f++) {
                float av = a_[f * 32];
                ull ap = pk2(av, av);
                acc[f][0] = fma2(ap, bp0, acc[f][0]);
                acc[f][1] = fma2(ap, bp1, acc[f][1]);
                acc[f][2] = fma2(ap, bp2, acc[f][2]);
                acc[f][3] = fma2(ap, bp3, acc[f][3]);
            }
        }
    }

    float a_s[8], a_d[8];
#pragma unroll
    for (int j = 0; j < 8; j++) {
        a_s[j] = __ldg(&asrc[w * 8 + j]);
        a_d[j] = __ldg(&adst[w * 8 + j]);
    }
    float* sAl = sm;
    __syncthreads();
    for (int i = tid; i < 192 * 8; i += 384) sAl[i] = 0.f;
    __syncthreads();

#pragma unroll
    for (int f = 0; f < 6; f++) {
        int r = lane + f * 32;
        int row = row0 + r;
        float o0x, o0y, o0z, o0w, o1x, o1y, o1z, o1w;
        upk2(acc[f][0], o0x, o0y);
        upk2(acc[f][1], o0z, o0w);
        upk2(acc[f][2], o1x, o1y);
        upk2(acc[f][3], o1z, o1w);
        if (row < n) {
            union { __half2 h[4]; uint4 u; } pk;
            pk.h[0] = __floats2half2_rn(o0x, o0y);
            pk.h[1] = __floats2half2_rn(o0z, o0w);
            pk.h[2] = __floats2half2_rn(o1x, o1y);
            pk.h[3] = __floats2half2_rn(o1z, o1w);
            *(uint4*)(H2 + row * 48 + w * 4) = pk.u;   // 16B aligned
        }
        float sp = o0x * a_s[0] + o0y * a_s[1] + o0z * a_s[2] + o0w * a_s[3]
                 + o1x * a_s[4] + o1y * a_s[5] + o1z * a_s[6] + o1w * a_s[7];
        float dp = o0x * a_d[0] + o0y * a_d[1] + o0z * a_d[2] + o0w * a_d[3]
                 + o1x * a_d[4] + o1y * a_d[5] + o1z * a_d[6] + o1w * a_d[7];
        atomicAdd(&sAl[r * 8 + head], sp);
        atomicAdd(&sAl[r * 8 + 4 + head], dp);
    }
    __syncthreads();
    for (int i = tid; i < 192 * 4; i += 384) {
        int r = i >> 2, hh = i & 3;
        int row = row0 + r;
        if (row < n) {
            AS[row * 4 + hh] = sAl[r * 8 + hh];
            AD[row * 4 + hh] = sAl[r * 8 + 4 + hh];
        }
    }
}

// ================= fused softmax + aggregation (warp per dst, fp16 H gather) =================
#define DCAP 128
__global__ void k_sagg(const int* __restrict__ off, const int* __restrict__ srcs,
                       const float* __restrict__ AS, const float* __restrict__ AD,
                       const __half2* __restrict__ H2, const float* __restrict__ bias,
                       float* __restrict__ OUT, int n) {
    __shared__ int    ssrc[8][DCAP];
    __shared__ float4 slog[8][DCAP];
    int gtid = blockIdx.x * blockDim.x + threadIdx.x;
    int node = gtid >> 5, lane = gtid & 31;
    int ws = threadIdx.x >> 5;
    if (node >= n) return;
    int beg = __ldg(&off[node]), end = __ldg(&off[node + 1]);
    int deg = end - beg;
    float4 ad = *(const float4*)(AD + node * 4);

    bool act = lane < 24;
    int head = lane / 6;
    float4 acc = make_float4(0.f, 0.f, 0.f, 0.f);
    float4 den = make_float4(0.f, 0.f, 0.f, 0.f);
    float4 mx = make_float4(-INFINITY, -INFINITY, -INFINITY, -INFINITY);

    if (deg <= DCAP) {
        for (int j = lane; j < deg; j += 32) {
            int s = __ldg(&srcs[beg + j]);
            float4 a = *(const float4*)(AS + s * 4);
            float t; float4 v;
            t = a.x + ad.x; v.x = t > 0.f ? t : 0.2f * t; mx.x = fmaxf(mx.x, v.x);
            t = a.y + ad.y; v.y = t > 0.f ? t : 0.2f * t; mx.y = fmaxf(mx.y, v.y);
            t = a.z + ad.z; v.z = t > 0.f ? t : 0.2f * t; mx.z = fmaxf(mx.z, v.z);
            t = a.w + ad.w; v.w = t > 0.f ? t : 0.2f * t; mx.w = fmaxf(mx.w, v.w);
            ssrc[ws][j] = s;
            slog[ws][j] = v;
        }
#pragma unroll
        for (int o = 16; o > 0; o >>= 1) {
            mx.x = fmaxf(mx.x, __shfl_xor_sync(0xffffffffu, mx.x, o));
            mx.y = fmaxf(mx.y, __shfl_xor_sync(0xffffffffu, mx.y, o));
            mx.z = fmaxf(mx.z, __shfl_xor_sync(0xffffffffu, mx.z, o));
            mx.w = fmaxf(mx.w, __shfl_xor_sync(0xffffffffu, mx.w, o));
        }
        __syncwarp();
        for (int j = lane; j < deg; j += 32) {
            float4 v = slog[ws][j];
            float4 ex;
            ex.x = expf(v.x - mx.x); ex.y = expf(v.y - mx.y);
            ex.z = expf(v.z - mx.z); ex.w = expf(v.w - mx.w);
            slog[ws][j] = ex;
            den.x += ex.x; den.y += ex.y; den.z += ex.z; den.w += ex.w;
        }
        __syncwarp();
        if (act) {
            const float* sexf = (const float*)&slog[ws][0];
#pragma unroll 4
            for (int j = 0; j < deg; j++) {
                int s = ssrc[ws][j];
                float wv = sexf[j * 4 + head];
                uint2 raw = __ldg((const uint2*)(H2 + s * 48) + lane);
                float2 f01 = __half22float2(*(__half2*)&raw.x);
                float2 f23 = __half22float2(*(__half2*)&raw.y);
                acc.x = fmaf(f01.x, wv, acc.x);
                acc.y = fmaf(f01.y, wv, acc.y);
                acc.z = fmaf(f23.x, wv, acc.z);
                acc.w = fmaf(f23.y, wv, acc.w);
            }
        }
    } else {
        // rare fallback: two-pass chunked recompute
        for (int e = beg + lane; e < end; e += 32) {
            int s = __ldg(&srcs[e]);
            float4 a = *(const float4*)(AS + s * 4);
            float t;
            t = a.x + ad.x; t = t > 0.f ? t : 0.2f * t; mx.x = fmaxf(mx.x, t);
            t = a.y + ad.y; t = t > 0.f ? t : 0.2f * t; mx.y = fmaxf(mx.y, t);
            t = a.z + ad.z; t = t > 0.f ? t : 0.2f * t; mx.z = fmaxf(mx.z, t);
            t = a.w + ad.w; t = t > 0.f ? t : 0.2f * t; mx.w = fmaxf(mx.w, t);
        }
#pragma unroll
        for (int o = 16; o > 0; o >>= 1) {
            mx.x = fmaxf(mx.x, __shfl_xor_sync(0xffffffffu, mx.x, o));
            mx.y = fmaxf(mx.y, __shfl_xor_sync(0xffffffffu, mx.y, o));
            mx.z = fmaxf(mx.z, __shfl_xor_sync(0xffffffffu, mx.z, o));
            mx.w = fmaxf(mx.w, __shfl_xor_sync(0xffffffffu, mx.w, o));
        }
        for (int c0 = beg; c0 < end; c0 += 32) {
            int e = c0 + lane;
            if (e < end) {
                int s = __ldg(&srcs[e]);
                float4 a = *(const float4*)(AS + s * 4);
                float t; float4 ex;
                t = a.x + ad.x; t = t > 0.f ? t : 0.2f * t; ex.x = expf(t - mx.x);
                t = a.y + ad.y; t = t > 0.f ? t : 0.2f * t; ex.y = expf(t - mx.y);
                t = a.z + ad.z; t = t > 0.f ? t : 0.2f * t; ex.z = expf(t - mx.z);
                t = a.w + ad.w; t = t > 0.f ? t : 0.2f * t; ex.w = expf(t - mx.w);
                den.x += ex.x; den.y += ex.y; den.z += ex.z; den.w += ex.w;
                ssrc[ws][lane] = s;
                slog[ws][lane] = ex;
            }
            __syncwarp();
            int cnt = min(32, end - c0);
            if (act) {
                const float* sexf = (const float*)&slog[ws][0];
                for (int j = 0; j < cnt; j++) {
                    int s = ssrc[ws][j];
                    float wv = sexf[j * 4 + head];
                    uint2 raw = __ldg((const uint2*)(H2 + s * 48) + lane);
                    float2 f01 = __half22float2(*(__half2*)&raw.x);
                    float2 f23 = __half22float2(*(__half2*)&raw.y);
                    acc.x = fmaf(f01.x, wv, acc.x);
                    acc.y = fmaf(f01.y, wv, acc.y);
                    acc.z = fmaf(f23.x, wv, acc.z);
                    acc.w = fmaf(f23.y, wv, acc.w);
                }
            }
            __syncwarp();
        }
    }

#pragma unroll
    for (int o = 16; o > 0; o >>= 1) {
        den.x += __shfl_xor_sync(0xffffffffu, den.x, o);
        den.y += __shfl_xor_sync(0xffffffffu, den.y, o);
        den.z += __shfl_xor_sync(0xffffffffu, den.z, o);
        den.w += __shfl_xor_sync(0xffffffffu, den.w, o);
    }
    if (act) {
        float dh = head == 0 ? den.x : (head == 1 ? den.y : (head == 2 ? den.z : den.w));
        float inv = 1.f / (dh + 1e-16f);
        float4 b4 = *(const float4*)(bias + lane * 4);
        float4 o;
        o.x = acc.x * inv + b4.x;  o.x = o.x > 0.f ? o.x : expm1f(o.x);
        o.y = acc.y * inv + b4.y;  o.y = o.y > 0.f ? o.y : expm1f(o.y);
        o.z = acc.z * inv + b4.z;  o.z = o.z > 0.f ? o.z : expm1f(o.z);
        o.w = acc.w * inv + b4.w;  o.w = o.w > 0.f ? o.w : expm1f(o.w);
        *(float4*)(OUT + node * 96 + lane * 4) = o;
    }
}

// ================= gate MLP: smem weights, 2 nodes per warp =================
__global__ void k_gate(const float* __restrict__ H, const float* __restrict__ gw1,
                       const float* __restrict__ gb1, const float* __restrict__ gw2,
                       const float* __restrict__ gb2, const int* __restrict__ batch,
                       float* __restrict__ GATE, float* __restrict__ GM, int n) {
    __shared__ float sw1[96 * 48];
    __shared__ float sb1[48], sg2[48];
    int tid = threadIdx.x;
    for (int i = tid; i < 96 * 48; i += 256) sw1[i] = gw1[i];
    if (tid < 48) { sb1[tid] = gb1[tid]; sg2[tid] = gw2[tid]; }
    __syncthreads();
    int w = tid >> 5, lane = tid & 31;
    int base = blockIdx.x * 64;
    for (int it = 0; it < 4; it++) {
        int nodeA = base + it * 16 + w * 2;
        int nodeB = nodeA + 1;
        bool vA = nodeA < n, vB = nodeB < n;
        if (!vA) return;
        float a0 = 0.f, a1 = 0.f, b0 = 0.f, b1 = 0.f;
        const float* hA = H + nodeA * 96;
        const float* hB = H + nodeB * 96;
        for (int k = 0; k < 96; k++) {
            float w0 = sw1[k * 48 + lane];
            float hv0 = __ldg(&hA[k]);
            a0 = fmaf(hv0, w0, a0);
            float hv1 = vB ? __ldg(&hB[k]) : 0.f;
            b0 = fmaf(hv1, w0, b0);
            if (lane < 16) {
                float w1 = sw1[k * 48 + 32 + lane];
                a1 = fmaf(hv0, w1, a1);
                b1 = fmaf(hv1, w1, b1);
            }
        }
        float gA = fmaxf(a0 + sb1[lane], 0.f) * sg2[lane];
        float gB = fmaxf(b0 + sb1[lane], 0.f) * sg2[lane];
        if (lane < 16) {
            gA += fmaxf(a1 + sb1[32 + lane], 0.f) * sg2[32 + lane];
            gB += fmaxf(b1 + sb1[32 + lane], 0.f) * sg2[32 + lane];
        }
#pragma unroll
        for (int o = 16; o > 0; o >>= 1) {
            gA += __shfl_xor_sync(0xffffffffu, gA, o);
            gB += __shfl_xor_sync(0xffffffffu, gB, o);
        }
        if (lane == 0) {
            gA += gb2[0];
            GATE[nodeA] = gA;
            atomicMaxF(&GM[batch[nodeA]], gA);
        }
        if (lane == 1 && vB) {
            gB += gb2[0];
            GATE[nodeB] = gB;
            atomicMaxF(&GM[batch[nodeB]], gB);
        }
    }
}

__global__ void k_gate_exp(const float* __restrict__ GATE, const float* __restrict__ GM,
                           const int* __restrict__ batch, float* __restrict__ GE,
                           float* __restrict__ GDEN, int n) {
    __shared__ float sden[GG];
    for (int i = threadIdx.x; i < GG; i += blockDim.x) sden[i] = 0.f;
    __syncthreads();
    int i = blockIdx.x * blockDim.x + threadIdx.x;
    if (i < n) {
        int b = batch[i];
        float m = GM[b];
        if (m == -INFINITY) m = 0.f;
        float e = expf(GATE[i] - m);
        GE[i] = e;
        atomicAdd(&sden[b], e);
    }
    __syncthreads();
    for (int i2 = threadIdx.x; i2 < GG; i2 += blockDim.x)
        if (sden[i2] != 0.f) atomicAdd(&GDEN[i2], sden[i2]);
}

// ================= pooling: 8 blocks per graph -> disjoint partials =================
__global__ void k_pool2(const float* __restrict__ H, const float* __restrict__ GE,
                        const float* __restrict__ GDEN, const int* __restrict__ batch,
                        float* __restrict__ POOL, int n) {
    __shared__ float red[192];
    int g = blockIdx.x;
    int part = blockIdx.y;
    int tid = threadIdx.x;
    int lo = 0, hi = n;
    while (lo < hi) { int mid = (lo + hi) >> 1; if (__ldg(&batch[mid]) < g) lo = mid + 1; else hi = mid; }
    int beg = lo;
    lo = beg; hi = n;
    while (lo < hi) { int mid = (lo + hi) >> 1; if (__ldg(&batch[mid]) < g + 1) lo = mid + 1; else hi = mid; }
    int end = lo;

    float invden = 1.f / (GDEN[g] + 1e-16f);
    int half = tid / 96, c = tid - half * 96;
    float acc = 0.f;
    for (int node = beg + part * 2 + half; node < end; node += 16) {
        float wv = __ldg(&GE[node]) * invden;
        acc = fmaf(__ldg(&H[node * 96 + c]), wv, acc);
    }
    red[tid] = acc;
    __syncthreads();
    if (tid < 96) POOL[(g * 8 + part) * 96 + tid] = red[tid] + red[tid + 96];
}

__global__ void k_final(const float* __restrict__ POOL, const float* __restrict__ fw1,
                        const float* __restrict__ fb1, const float* __restrict__ fw2,
                        const float* __restrict__ fb2, float* __restrict__ out) {
    __shared__ float pr[96];
    __shared__ float hid[96];
    int g = blockIdx.x, j = threadIdx.x;
    float p = 0.f;
#pragma unroll
    for (int q = 0; q < 8; q++) p += POOL[(g * 8 + q) * 96 + j];
    pr[j] = p;
    __syncthreads();
    float a = fb1[j];
#pragma unroll 8
    for (int k = 0; k < 96; k++) a += pr[k] * fw1[k * 96 + j];
    hid[j] = fmaxf(a, 0.f);
    __syncthreads();
    if (j < 3) {
        float o = fb2[j];
        for (int k = 0; k < 96; k++) o += hid[k] * fw2[k * 3 + j];
        out[g * 3 + j] = o;
    }
}

// ================= host =================
extern "C" void kernel_launch(void* const* d_in, const int* in_sizes, int n_in,
                              void* d_out, int out_size) {
    const float* x     = (const float*)d_in[0];
    const int*   ei    = (const int*)d_in[1];
    const int*   batch = (const int*)d_in[2];
    int idx = 3;
    if (n_in > 3 && in_sizes[3] == 1) idx = 4;
    const float* W1  = (const float*)d_in[idx++];
    const float* as1 = (const float*)d_in[idx++];
    const float* ad1 = (const float*)d_in[idx++];
    const float* b1  = (const float*)d_in[idx++];
    const float* W2  = (const float*)d_in[idx++];
    const float* as2 = (const float*)d_in[idx++];
    const float* ad2 = (const float*)d_in[idx++];
    const float* b2  = (const float*)d_in[idx++];
    const float* gw1 = (const float*)d_in[idx++];
    const float* gb1 = (const float*)d_in[idx++];
    const float* gw2 = (const float*)d_in[idx++];
    const float* gb2 = (const float*)d_in[idx++];
    const float* fw1 = (const float*)d_in[idx++];
    const float* fb1 = (const float*)d_in[idx++];
    const float* fw2 = (const float*)d_in[idx++];
    const float* fb2 = (const float*)d_in[idx++];

    int n    = in_sizes[0] / 128;
    int eraw = in_sizes[1] / 2;
    int etot = eraw + n;

    float *o, *as_, *ad_, *gate, *ge, *gm, *gden, *pool;
    __half2* h2;
    int *deg, *part, *bsum, *off, *srcs;
    cudaGetSymbolAddress((void**)&h2,   d_h2);
    cudaGetSymbolAddress((void**)&o,    d_o);
    cudaGetSymbolAddress((void**)&as_,  d_as);
    cudaGetSymbolAddress((void**)&ad_,  d_ad);
    cudaGetSymbolAddress((void**)&gate, d_gate);
    cudaGetSymbolAddress((void**)&ge,   d_ge);
    cudaGetSymbolAddress((void**)&gm,   d_gm);
    cudaGetSymbolAddress((void**)&gden, d_gden);
    cudaGetSymbolAddress((void**)&pool, d_pool);
    cudaGetSymbolAddress((void**)&deg,  d_deg);
    cudaGetSymbolAddress((void**)&part, d_part);
    cudaGetSymbolAddress((void**)&bsum, d_bsum);
    cudaGetSymbolAddress((void**)&off,  d_off);
    cudaGetSymbolAddress((void**)&srcs, d_srcs);

    int smem1 = (128 * 96 + 64 * 193) * 4;
    int smem2 = (96 * 96 + 96 * 193) * 4;
    cudaFuncSetAttribute(k_gemm2<128, 64>, cudaFuncAttributeMaxDynamicSharedMemorySize, smem1);
    cudaFuncSetAttribute(k_gemm2<96, 96>,  cudaFuncAttributeMaxDynamicSharedMemorySize, smem2);

    int gEdge  = (etot + 255) / 256;
    int gWarp  = (n * 32 + 255) / 256;
    int gGemm  = (n + 191) / 192;
    int gNode  = (n + 255) / 256;
    int gScan  = (n + 1023) / 1024;

    // ---- CSR build ----
    cudaMemsetAsync(deg, 0, n * sizeof(int));
    k_hist<<<gEdge, 256>>>(ei, deg, etot, eraw);
    k_scanA<<<gScan, 1024>>>(deg, part, bsum, n);
    k_scanB<<<1, 64>>>(bsum, gScan);
    k_scanC<<<gScan, 1024>>>(part, bsum, off, deg, gm, gden, n, etot);
    k_scatter<<<gEdge, 256>>>(ei, deg, srcs, etot, eraw);

    // ---- layer 1 ----
    k_gemm2<128, 64><<<gGemm, 384, smem1>>>(x, W1, as1, ad1, h2, as_, ad_, n);
    k_sagg<<<gWarp, 256>>>(off, srcs, as_, ad_, h2, b1, o, n);

    // ---- layer 2 ----
    k_gemm2<96, 96><<<gGemm, 384, smem2>>>(o, W2, as2, ad2, h2, as_, ad_, n);
    k_sagg<<<gWarp, 256>>>(off, srcs, as_, ad_, h2, b2, o, n);

    // ---- global attention pool + final MLP ----
    k_gate<<<(n + 63) / 64, 256>>>(o, gw1, gb1, gw2, gb2, batch, gate, gm, n);
    k_gate_exp<<<gNode, 256>>>(gate, gm, batch, ge, gden, n);
    k_pool2<<<dim3(GG, 8), 192>>>(o, ge, gden, batch, pool, n);
    k_final<<<GG, 96>>>(pool, fw1, fb1, fw2, fb2, (float*)d_out);
}

// round 10
// speedup vs baseline: 1.1652x; 1.0473x over previous
#include <cuda_runtime.h>
#include <cuda_fp16.h>
#include <math.h>

#define NN 50000
#define EE 800000
#define ETOT (EE + NN)
#define GG 64

// ---------------- scratch ----------------
__device__ __half2 d_h2[NN * 48];   // fp16 message matrix (H), 48 half2 per row
__device__ float d_o[NN * 96];
__device__ float d_as[NN * 4];
__device__ float d_ad[NN * 4];
__device__ int   d_deg[NN];
__device__ int   d_part[NN];
__device__ int   d_bsum[64];
__device__ int   d_off[NN + 1];
__device__ int   d_srcs[ETOT];
__device__ float d_gate[NN];
__device__ float d_ge[NN];
__device__ float d_gm[GG];
__device__ float d_gden[GG];
__device__ float d_pool[GG * 8 * 96];

__device__ __forceinline__ void atomicMaxF(float* a, float v) {
    if (v >= 0.f) atomicMax((int*)a, __float_as_int(v));
    else          atomicMin((unsigned int*)a, __float_as_uint(v));
}

typedef unsigned long long ull;
__device__ __forceinline__ ull pk2(float x, float y) {
    ull r;
    asm("mov.b64 %0, {%1, %2};" : "=l"(r) : "f"(x), "f"(y));
    return r;
}
__device__ __forceinline__ ull fma2(ull a, ull b, ull c) {
    ull d;
    asm("fma.rn.f32x2 %0, %1, %2, %3;" : "=l"(d) : "l"(a), "l"(b), "l"(c));
    return d;
}
__device__ __forceinline__ void upk2(ull v, float& x, float& y) {
    asm("mov.b64 {%0, %1}, %2;" : "=f"(x), "=f"(y) : "l"(v));
}

// ================= CSR build =================
__global__ void k_hist(const int* __restrict__ ei, int* __restrict__ deg, int etot, int eraw) {
    int e = blockIdx.x * blockDim.x + threadIdx.x;
    if (e >= etot) return;
    int d = (e < eraw) ? __ldg(&ei[eraw + e]) : e - eraw;
    atomicAdd(&deg[d], 1);
}

__global__ void k_scanA(const int* __restrict__ deg, int* __restrict__ part,
                        int* __restrict__ bsum, int n) {
    __shared__ int wsum[32];
    int t = threadIdx.x;
    int i = blockIdx.x * 1024 + t;
    int v = (i < n) ? deg[i] : 0;
    int lane = t & 31, w = t >> 5;
    int x = v;
#pragma unroll
    for (int o = 1; o < 32; o <<= 1) {
        int y = __shfl_up_sync(0xffffffffu, x, o);
        if (lane >= o) x += y;
    }
    if (lane == 31) wsum[w] = x;
    __syncthreads();
    if (w == 0) {
        int s = wsum[lane];
#pragma unroll
        for (int o = 1; o < 32; o <<= 1) {
            int y = __shfl_up_sync(0xffffffffu, s, o);
            if (lane >= o) s += y;
        }
        wsum[lane] = s;
    }
    __syncthreads();
    int woff = (w > 0) ? wsum[w - 1] : 0;
    if (i < n) part[i] = x - v + woff;
    if (t == 0) bsum[blockIdx.x] = wsum[31];
}

__global__ void k_scanB(int* __restrict__ bsum, int nb) {
    __shared__ int w0tot;
    int t = threadIdx.x;
    int lane = t & 31, w = t >> 5;
    int v = (t < nb) ? bsum[t] : 0;
    int x = v;
#pragma unroll
    for (int o = 1; o < 32; o <<= 1) {
        int y = __shfl_up_sync(0xffffffffu, x, o);
        if (lane >= o) x += y;
    }
    if (w == 0 && lane == 31) w0tot = x;
    __syncthreads();
    if (w == 1) x += w0tot;
    if (t < nb) bsum[t] = x - v;
}

__global__ void k_scanC(const int* __restrict__ part, const int* __restrict__ bsum,
                        int* __restrict__ off, int* __restrict__ cur,
                        float* __restrict__ GM, float* __restrict__ GDEN,
                        int n, int etot) {
    int i = blockIdx.x * 1024 + threadIdx.x;
    if (i < n) {
        int v = part[i] + bsum[blockIdx.x];
        off[i] = v;
        cur[i] = v;
    }
    if (i == 0) off[n] = etot;
    if (blockIdx.x == 0 && threadIdx.x < GG) {
        GM[threadIdx.x] = -INFINITY;
        GDEN[threadIdx.x] = 0.f;
    }
}

__global__ void k_scatter(const int* __restrict__ ei, int* __restrict__ cur,
                          int* __restrict__ srcs, int etot, int eraw) {
    int e = blockIdx.x * blockDim.x + threadIdx.x;
    if (e >= etot) return;
    int s, d;
    if (e < eraw) { s = __ldg(&ei[e]); d = __ldg(&ei[eraw + e]); }
    else          { s = d = e - eraw; }
    int pos = atomicAdd(&cur[d], 1);
    srcs[pos] = s;
}

// ================= GEMM + fused alpha epilogue (H stored fp16) =================
template<int K, int KC>
__global__ void __launch_bounds__(384, 2) k_gemm2(const float* __restrict__ A,
                                                  const float* __restrict__ W,
                                                  const float* __restrict__ asrc,
                                                  const float* __restrict__ adst,
                                                  __half2* __restrict__ H2,
                                                  float* __restrict__ AS,
                                                  float* __restrict__ AD, int n) {
    extern __shared__ float sm[];
    float* Bs = sm;              // K*96 (full weights, global-k)
    float* As = sm + K * 96;     // KC*193
    int tid = threadIdx.x;
    int w = tid >> 5, lane = tid & 31;
    int row0 = blockIdx.x * 192;
    int head = w / 3;

    ull acc[6][4];
#pragma unroll
    for (int f = 0; f < 6; f++)
#pragma unroll
        for (int j = 0; j < 4; j++) acc[f][j] = 0ull;

    for (int i = tid; i < K * 96; i += 384) Bs[i] = W[i];

    for (int k0 = 0; k0 < K; k0 += KC) {
        __syncthreads();
        for (int i = tid; i < 192 * KC; i += 384) {
            int k = i % KC, r = i / KC;
            int row = row0 + r;
            As[k * 193 + r] = (row < n) ? A[row * K + k0 + k] : 0.f;
        }
        __syncthreads();
#pragma unroll 8
        for (int k = 0; k < KC; k++) {
            const ull* b_ = (const ull*)&Bs[(k0 + k) * 96 + w * 8];
            ull bp0 = b_[0], bp1 = b_[1], bp2 = b_[2], bp3 = b_[3];
            const float* a_ = &As[k * 193 + lane];
#pragma unroll
            for (int f = 0; f < 6; f++) {
                float av = a_[f * 32];
                ull ap = pk2(av, av);
                acc[f][0] = fma2(ap, bp0, acc[f][0]);
                acc[f][1] = fma2(ap, bp1, acc[f][1]);
                acc[f][2] = fma2(ap, bp2, acc[f][2]);
                acc[f][3] = fma2(ap, bp3, acc[f][3]);
            }
        }
    }

    float a_s[8], a_d[8];
#pragma unroll
    for (int j = 0; j < 8; j++) {
        a_s[j] = __ldg(&asrc[w * 8 + j]);
        a_d[j] = __ldg(&adst[w * 8 + j]);
    }
    float* sAl = sm;
    __syncthreads();
    for (int i = tid; i < 192 * 8; i += 384) sAl[i] = 0.f;
    __syncthreads();

#pragma unroll
    for (int f = 0; f < 6; f++) {
        int r = lane + f * 32;
        int row = row0 + r;
        float o0x, o0y, o0z, o0w, o1x, o1y, o1z, o1w;
        upk2(acc[f][0], o0x, o0y);
        upk2(acc[f][1], o0z, o0w);
        upk2(acc[f][2], o1x, o1y);
        upk2(acc[f][3], o1z, o1w);
        if (row < n) {
            union { __half2 h[4]; uint4 u; } pk;
            pk.h[0] = __floats2half2_rn(o0x, o0y);
            pk.h[1] = __floats2half2_rn(o0z, o0w);
            pk.h[2] = __floats2half2_rn(o1x, o1y);
            pk.h[3] = __floats2half2_rn(o1z, o1w);
            *(uint4*)(H2 + row * 48 + w * 4) = pk.u;
        }
        float sp = o0x * a_s[0] + o0y * a_s[1] + o0z * a_s[2] + o0w * a_s[3]
                 + o1x * a_s[4] + o1y * a_s[5] + o1z * a_s[6] + o1w * a_s[7];
        float dp = o0x * a_d[0] + o0y * a_d[1] + o0z * a_d[2] + o0w * a_d[3]
                 + o1x * a_d[4] + o1y * a_d[5] + o1z * a_d[6] + o1w * a_d[7];
        atomicAdd(&sAl[r * 8 + head], sp);
        atomicAdd(&sAl[r * 8 + 4 + head], dp);
    }
    __syncthreads();
    for (int i = tid; i < 192 * 4; i += 384) {
        int r = i >> 2, hh = i & 3;
        int row = row0 + r;
        if (row < n) {
            AS[row * 4 + hh] = sAl[r * 8 + hh];
            AD[row * 4 + hh] = sAl[r * 8 + 4 + hh];
        }
    }
}

// ================= fused softmax + aggregation (warp per dst, fp16 H gather) =================
#define DCAP 128
__global__ void k_sagg(const int* __restrict__ off, const int* __restrict__ srcs,
                       const float* __restrict__ AS, const float* __restrict__ AD,
                       const __half2* __restrict__ H2, const float* __restrict__ bias,
                       float* __restrict__ OUT, int n) {
    __shared__ int    ssrc[8][DCAP];
    __shared__ float4 slog[8][DCAP];
    int gtid = blockIdx.x * blockDim.x + threadIdx.x;
    int node = gtid >> 5, lane = gtid & 31;
    int ws = threadIdx.x >> 5;
    if (node >= n) return;
    int beg = __ldg(&off[node]), end = __ldg(&off[node + 1]);
    int deg = end - beg;
    float4 ad = *(const float4*)(AD + node * 4);

    bool act = lane < 24;
    int head = lane / 6;
    float4 acc = make_float4(0.f, 0.f, 0.f, 0.f);
    float4 den = make_float4(0.f, 0.f, 0.f, 0.f);
    float4 mx = make_float4(-INFINITY, -INFINITY, -INFINITY, -INFINITY);

    if (deg <= DCAP) {
        for (int j = lane; j < deg; j += 32) {
            int s = __ldg(&srcs[beg + j]);
            float4 a = *(const float4*)(AS + s * 4);
            float t; float4 v;
            t = a.x + ad.x; v.x = t > 0.f ? t : 0.2f * t; mx.x = fmaxf(mx.x, v.x);
            t = a.y + ad.y; v.y = t > 0.f ? t : 0.2f * t; mx.y = fmaxf(mx.y, v.y);
            t = a.z + ad.z; v.z = t > 0.f ? t : 0.2f * t; mx.z = fmaxf(mx.z, v.z);
            t = a.w + ad.w; v.w = t > 0.f ? t : 0.2f * t; mx.w = fmaxf(mx.w, v.w);
            ssrc[ws][j] = s;
            slog[ws][j] = v;
        }
#pragma unroll
        for (int o = 16; o > 0; o >>= 1) {
            mx.x = fmaxf(mx.x, __shfl_xor_sync(0xffffffffu, mx.x, o));
            mx.y = fmaxf(mx.y, __shfl_xor_sync(0xffffffffu, mx.y, o));
            mx.z = fmaxf(mx.z, __shfl_xor_sync(0xffffffffu, mx.z, o));
            mx.w = fmaxf(mx.w, __shfl_xor_sync(0xffffffffu, mx.w, o));
        }
        __syncwarp();
        for (int j = lane; j < deg; j += 32) {
            float4 v = slog[ws][j];
            float4 ex;
            ex.x = expf(v.x - mx.x); ex.y = expf(v.y - mx.y);
            ex.z = expf(v.z - mx.z); ex.w = expf(v.w - mx.w);
            slog[ws][j] = ex;
            den.x += ex.x; den.y += ex.y; den.z += ex.z; den.w += ex.w;
        }
        __syncwarp();
        if (act) {
            const float* sexf = (const float*)&slog[ws][0];
#pragma unroll 4
            for (int j = 0; j < deg; j++) {
                int s = ssrc[ws][j];
                float wv = sexf[j * 4 + head];
                uint2 raw = __ldg((const uint2*)(H2 + s * 48) + lane);
                float2 f01 = __half22float2(*(__half2*)&raw.x);
                float2 f23 = __half22float2(*(__half2*)&raw.y);
                acc.x = fmaf(f01.x, wv, acc.x);
                acc.y = fmaf(f01.y, wv, acc.y);
                acc.z = fmaf(f23.x, wv, acc.z);
                acc.w = fmaf(f23.y, wv, acc.w);
            }
        }
    } else {
        for (int e = beg + lane; e < end; e += 32) {
            int s = __ldg(&srcs[e]);
            float4 a = *(const float4*)(AS + s * 4);
            float t;
            t = a.x + ad.x; t = t > 0.f ? t : 0.2f * t; mx.x = fmaxf(mx.x, t);
            t = a.y + ad.y; t = t > 0.f ? t : 0.2f * t; mx.y = fmaxf(mx.y, t);
            t = a.z + ad.z; t = t > 0.f ? t : 0.2f * t; mx.z = fmaxf(mx.z, t);
            t = a.w + ad.w; t = t > 0.f ? t : 0.2f * t; mx.w = fmaxf(mx.w, t);
        }
#pragma unroll
        for (int o = 16; o > 0; o >>= 1) {
            mx.x = fmaxf(mx.x, __shfl_xor_sync(0xffffffffu, mx.x, o));
            mx.y = fmaxf(mx.y, __shfl_xor_sync(0xffffffffu, mx.y, o));
            mx.z = fmaxf(mx.z, __shfl_xor_sync(0xffffffffu, mx.z, o));
            mx.w = fmaxf(mx.w, __shfl_xor_sync(0xffffffffu, mx.w, o));
        }
        for (int c0 = beg; c0 < end; c0 += 32) {
            int e = c0 + lane;
            if (e < end) {
                int s = __ldg(&srcs[e]);
                float4 a = *(const float4*)(AS + s * 4);
                float t; float4 ex;
                t = a.x + ad.x; t = t > 0.f ? t : 0.2f * t; ex.x = expf(t - mx.x);
                t = a.y + ad.y; t = t > 0.f ? t : 0.2f * t; ex.y = expf(t - mx.y);
                t = a.z + ad.z; t = t > 0.f ? t : 0.2f * t; ex.z = expf(t - mx.z);
                t = a.w + ad.w; t = t > 0.f ? t : 0.2f * t; ex.w = expf(t - mx.w);
                den.x += ex.x; den.y += ex.y; den.z += ex.z; den.w += ex.w;
                ssrc[ws][lane] = s;
                slog[ws][lane] = ex;
            }
            __syncwarp();
            int cnt = min(32, end - c0);
            if (act) {
                const float* sexf = (const float*)&slog[ws][0];
                for (int j = 0; j < cnt; j++) {
                    int s = ssrc[ws][j];
                    float wv = sexf[j * 4 + head];
                    uint2 raw = __ldg((const uint2*)(H2 + s * 48) + lane);
                    float2 f01 = __half22float2(*(__half2*)&raw.x);
                    float2 f23 = __half22float2(*(__half2*)&raw.y);
                    acc.x = fmaf(f01.x, wv, acc.x);
                    acc.y = fmaf(f01.y, wv, acc.y);
                    acc.z = fmaf(f23.x, wv, acc.z);
                    acc.w = fmaf(f23.y, wv, acc.w);
                }
            }
            __syncwarp();
        }
    }

#pragma unroll
    for (int o = 16; o > 0; o >>= 1) {
        den.x += __shfl_xor_sync(0xffffffffu, den.x, o);
        den.y += __shfl_xor_sync(0xffffffffu, den.y, o);
        den.z += __shfl_xor_sync(0xffffffffu, den.z, o);
        den.w += __shfl_xor_sync(0xffffffffu, den.w, o);
    }
    if (act) {
        float dh = head == 0 ? den.x : (head == 1 ? den.y : (head == 2 ? den.z : den.w));
        float inv = 1.f / (dh + 1e-16f);
        float4 b4 = *(const float4*)(bias + lane * 4);
        float4 o;
        o.x = acc.x * inv + b4.x;  o.x = o.x > 0.f ? o.x : expm1f(o.x);
        o.y = acc.y * inv + b4.y;  o.y = o.y > 0.f ? o.y : expm1f(o.y);
        o.z = acc.z * inv + b4.z;  o.z = o.z > 0.f ? o.z : expm1f(o.z);
        o.w = acc.w * inv + b4.w;  o.w = o.w > 0.f ? o.w : expm1f(o.w);
        *(float4*)(OUT + node * 96 + lane * 4) = o;
    }
}

// ================= gate MLP: smem weights, 2 nodes per warp =================
__global__ void k_gate(const float* __restrict__ H, const float* __restrict__ gw1,
                       const float* __restrict__ gb1, const float* __restrict__ gw2,
                       const float* __restrict__ gb2, const int* __restrict__ batch,
                       float* __restrict__ GATE, float* __restrict__ GM, int n) {
    __shared__ float sw1[96 * 48];
    __shared__ float sb1[48], sg2[48];
    int tid = threadIdx.x;
    for (int i = tid; i < 96 * 48; i += 256) sw1[i] = gw1[i];
    if (tid < 48) { sb1[tid] = gb1[tid]; sg2[tid] = gw2[tid]; }
    __syncthreads();
    int w = tid >> 5, lane = tid & 31;
    int base = blockIdx.x * 64;
    for (int it = 0; it < 4; it++) {
        int nodeA = base + it * 16 + w * 2;
        int nodeB = nodeA + 1;
        bool vA = nodeA < n, vB = nodeB < n;
        if (!vA) return;
        float a0 = 0.f, a1 = 0.f, b0 = 0.f, b1 = 0.f;
        const float* hA = H + nodeA * 96;
        const float* hB = H + nodeB * 96;
        for (int k = 0; k < 96; k++) {
            float w0 = sw1[k * 48 + lane];
            float hv0 = __ldg(&hA[k]);
            a0 = fmaf(hv0, w0, a0);
            float hv1 = vB ? __ldg(&hB[k]) : 0.f;
            b0 = fmaf(hv1, w0, b0);
            if (lane < 16) {
                float w1 = sw1[k * 48 + 32 + lane];
                a1 = fmaf(hv0, w1, a1);
                b1 = fmaf(hv1, w1, b1);
            }
        }
        float gA = fmaxf(a0 + sb1[lane], 0.f) * sg2[lane];
        float gB = fmaxf(b0 + sb1[lane], 0.f) * sg2[lane];
        if (lane < 16) {
            gA += fmaxf(a1 + sb1[32 + lane], 0.f) * sg2[32 + lane];
            gB += fmaxf(b1 + sb1[32 + lane], 0.f) * sg2[32 + lane];
        }
#pragma unroll
        for (int o = 16; o > 0; o >>= 1) {
            gA += __shfl_xor_sync(0xffffffffu, gA, o);
            gB += __shfl_xor_sync(0xffffffffu, gB, o);
        }
        if (lane == 0) {
            gA += gb2[0];
            GATE[nodeA] = gA;
            atomicMaxF(&GM[batch[nodeA]], gA);
        }
        if (lane == 1 && vB) {
            gB += gb2[0];
            GATE[nodeB] = gB;
            atomicMaxF(&GM[batch[nodeB]], gB);
        }
    }
}

__global__ void k_gate_exp(const float* __restrict__ GATE, const float* __restrict__ GM,
                           const int* __restrict__ batch, float* __restrict__ GE,
                           float* __restrict__ GDEN, int n) {
    __shared__ float sden[GG];
    for (int i = threadIdx.x; i < GG; i += blockDim.x) sden[i] = 0.f;
    __syncthreads();
    int i = blockIdx.x * blockDim.x + threadIdx.x;
    if (i < n) {
        int b = batch[i];
        float m = GM[b];
        if (m == -INFINITY) m = 0.f;
        float e = expf(GATE[i] - m);
        GE[i] = e;
        atomicAdd(&sden[b], e);
    }
    __syncthreads();
    for (int i2 = threadIdx.x; i2 < GG; i2 += blockDim.x)
        if (sden[i2] != 0.f) atomicAdd(&GDEN[i2], sden[i2]);
}

// ================= pooling: 8 blocks per graph -> disjoint partials =================
__global__ void k_pool2(const float* __restrict__ H, const float* __restrict__ GE,
                        const float* __restrict__ GDEN, const int* __restrict__ batch,
                        float* __restrict__ POOL, int n) {
    __shared__ float red[192];
    int g = blockIdx.x;
    int part = blockIdx.y;
    int tid = threadIdx.x;
    int lo = 0, hi = n;
    while (lo < hi) { int mid = (lo + hi) >> 1; if (__ldg(&batch[mid]) < g) lo = mid + 1; else hi = mid; }
    int beg = lo;
    lo = beg; hi = n;
    while (lo < hi) { int mid = (lo + hi) >> 1; if (__ldg(&batch[mid]) < g + 1) lo = mid + 1; else hi = mid; }
    int end = lo;

    float invden = 1.f / (GDEN[g] + 1e-16f);
    int half = tid / 96, c = tid - half * 96;
    float acc = 0.f;
    for (int node = beg + part * 2 + half; node < end; node += 16) {
        float wv = __ldg(&GE[node]) * invden;
        acc = fmaf(__ldg(&H[node * 96 + c]), wv, acc);
    }
    red[tid] = acc;
    __syncthreads();
    if (tid < 96) POOL[(g * 8 + part) * 96 + tid] = red[tid] + red[tid + 96];
}

__global__ void k_final(const float* __restrict__ POOL, const float* __restrict__ fw1,
                        const float* __restrict__ fb1, const float* __restrict__ fw2,
                        const float* __restrict__ fb2, float* __restrict__ out) {
    __shared__ float pr[96];
    __shared__ float hid[96];
    int g = blockIdx.x, j = threadIdx.x;
    float p = 0.f;
#pragma unroll
    for (int q = 0; q < 8; q++) p += POOL[(g * 8 + q) * 96 + j];
    pr[j] = p;
    __syncthreads();
    float a = fb1[j];
#pragma unroll 8
    for (int k = 0; k < 96; k++) a += pr[k] * fw1[k * 96 + j];
    hid[j] = fmaxf(a, 0.f);
    __syncthreads();
    if (j < 3) {
        float o = fb2[j];
        for (int k = 0; k < 96; k++) o += hid[k] * fw2[k * 3 + j];
        out[g * 3 + j] = o;
    }
}

// ================= host =================
extern "C" void kernel_launch(void* const* d_in, const int* in_sizes, int n_in,
                              void* d_out, int out_size) {
    const float* x     = (const float*)d_in[0];
    const int*   ei    = (const int*)d_in[1];
    const int*   batch = (const int*)d_in[2];
    int idx = 3;
    if (n_in > 3 && in_sizes[3] == 1) idx = 4;
    const float* W1  = (const float*)d_in[idx++];
    const float* as1 = (const float*)d_in[idx++];
    const float* ad1 = (const float*)d_in[idx++];
    const float* b1  = (const float*)d_in[idx++];
    const float* W2  = (const float*)d_in[idx++];
    const float* as2 = (const float*)d_in[idx++];
    const float* ad2 = (const float*)d_in[idx++];
    const float* b2  = (const float*)d_in[idx++];
    const float* gw1 = (const float*)d_in[idx++];
    const float* gb1 = (const float*)d_in[idx++];
    const float* gw2 = (const float*)d_in[idx++];
    const float* gb2 = (const float*)d_in[idx++];
    const float* fw1 = (const float*)d_in[idx++];
    const float* fb1 = (const float*)d_in[idx++];
    const float* fw2 = (const float*)d_in[idx++];
    const float* fb2 = (const float*)d_in[idx++];

    int n    = in_sizes[0] / 128;
    int eraw = in_sizes[1] / 2;
    int etot = eraw + n;

    float *o, *as_, *ad_, *gate, *ge, *gm, *gden, *pool;
    __half2* h2;
    int *deg, *part, *bsum, *off, *srcs;
    cudaGetSymbolAddress((void**)&h2,   d_h2);
    cudaGetSymbolAddress((void**)&o,    d_o);
    cudaGetSymbolAddress((void**)&as_,  d_as);
    cudaGetSymbolAddress((void**)&ad_,  d_ad);
    cudaGetSymbolAddress((void**)&gate, d_gate);
    cudaGetSymbolAddress((void**)&ge,   d_ge);
    cudaGetSymbolAddress((void**)&gm,   d_gm);
    cudaGetSymbolAddress((void**)&gden, d_gden);
    cudaGetSymbolAddress((void**)&pool, d_pool);
    cudaGetSymbolAddress((void**)&deg,  d_deg);
    cudaGetSymbolAddress((void**)&part, d_part);
    cudaGetSymbolAddress((void**)&bsum, d_bsum);
    cudaGetSymbolAddress((void**)&off,  d_off);
    cudaGetSymbolAddress((void**)&srcs, d_srcs);

    int smem1 = (128 * 96 + 64 * 193) * 4;
    int smem2 = (96 * 96 + 96 * 193) * 4;
    cudaFuncSetAttribute(k_gemm2<128, 64>, cudaFuncAttributeMaxDynamicSharedMemorySize, smem1);
    cudaFuncSetAttribute(k_gemm2<96, 96>,  cudaFuncAttributeMaxDynamicSharedMemorySize, smem2);

    int gEdge  = (etot + 255) / 256;
    int gWarp  = (n * 32 + 255) / 256;
    int gGemm  = (n + 191) / 192;
    int gNode  = (n + 255) / 256;
    int gScan  = (n + 1023) / 1024;

    // side stream + events (created once, outside any graph capture)
    static cudaStream_t s1 = nullptr;
    static cudaEvent_t evFork = nullptr, evJoin = nullptr;
    if (s1 == nullptr) {
        cudaStreamCreateWithFlags(&s1, cudaStreamNonBlocking);
        cudaEventCreateWithFlags(&evFork, cudaEventDisableTiming);
        cudaEventCreateWithFlags(&evJoin, cudaEventDisableTiming);
    }

    // ---- fork: CSR build on side stream, layer-1 GEMM on main stream ----
    cudaEventRecord(evFork, 0);
    cudaStreamWaitEvent(s1, evFork, 0);

    cudaMemsetAsync(deg, 0, n * sizeof(int), s1);
    k_hist<<<gEdge, 256, 0, s1>>>(ei, deg, etot, eraw);
    k_scanA<<<gScan, 1024, 0, s1>>>(deg, part, bsum, n);
    k_scanB<<<1, 64, 0, s1>>>(bsum, gScan);
    k_scanC<<<gScan, 1024, 0, s1>>>(part, bsum, off, deg, gm, gden, n, etot);
    k_scatter<<<gEdge, 256, 0, s1>>>(ei, deg, srcs, etot, eraw);
    cudaEventRecord(evJoin, s1);

    k_gemm2<128, 64><<<gGemm, 384, smem1>>>(x, W1, as1, ad1, h2, as_, ad_, n);

    // ---- join, then edge phase ----
    cudaStreamWaitEvent(0, evJoin, 0);
    k_sagg<<<gWarp, 256>>>(off, srcs, as_, ad_, h2, b1, o, n);

    // ---- layer 2 ----
    k_gemm2<96, 96><<<gGemm, 384, smem2>>>(o, W2, as2, ad2, h2, as_, ad_, n);
    k_sagg<<<gWarp, 256>>>(off, srcs, as_, ad_, h2, b2, o, n);

    // ---- global attention pool + final MLP ----
    k_gate<<<(n + 63) / 64, 256>>>(o, gw1, gb1, gw2, gb2, batch, gate, gm, n);
    k_gate_exp<<<gNode, 256>>>(gate, gm, batch, ge, gden, n);
    k_pool2<<<dim3(GG, 8), 192>>>(o, ge, gden, batch, pool, n);
    k_final<<<GG, 96>>>(pool, fw1, fb1, fw2, fb2, (float*)d_out);
}

// round 11
// speedup vs baseline: 1.2240x; 1.0504x over previous
#include <cuda_runtime.h>
#include <cuda_fp16.h>
#include <math.h>

#define NN 50000
#define EE 800000
#define ETOT (EE + NN)
#define GG 64

// ---------------- scratch ----------------
__device__ __half2 d_h2[NN * 48];   // fp16 message matrix (H), 48 half2 per row
__device__ float d_o[NN * 96];
__device__ float d_as[NN * 4];
__device__ float d_ad[NN * 4];
__device__ int   d_deg[NN];
__device__ int   d_part[NN];
__device__ int   d_bsum[64];
__device__ int   d_off[NN + 1];
__device__ int   d_srcs[ETOT];
__device__ float d_gate[NN];
__device__ float d_ge[NN];
__device__ float d_gm[GG];
__device__ float d_gden[GG];
__device__ float d_pool[GG * 8 * 96];

__device__ __forceinline__ void atomicMaxF(float* a, float v) {
    if (v >= 0.f) atomicMax((int*)a, __float_as_int(v));
    else          atomicMin((unsigned int*)a, __float_as_uint(v));
}

typedef unsigned long long ull;
__device__ __forceinline__ ull pk2(float x, float y) {
    ull r;
    asm("mov.b64 %0, {%1, %2};" : "=l"(r) : "f"(x), "f"(y));
    return r;
}
__device__ __forceinline__ ull fma2(ull a, ull b, ull c) {
    ull d;
    asm("fma.rn.f32x2 %0, %1, %2, %3;" : "=l"(d) : "l"(a), "l"(b), "l"(c));
    return d;
}
__device__ __forceinline__ void upk2(ull v, float& x, float& y) {
    asm("mov.b64 {%0, %1}, %2;" : "=f"(x), "=f"(y) : "l"(v));
}

// ================= CSR build =================
__global__ void k_hist(const int* __restrict__ ei, int* __restrict__ deg, int etot, int eraw) {
    int e = blockIdx.x * blockDim.x + threadIdx.x;
    if (e >= etot) return;
    int d = (e < eraw) ? __ldg(&ei[eraw + e]) : e - eraw;
    atomicAdd(&deg[d], 1);
}

__global__ void k_scanA(const int* __restrict__ deg, int* __restrict__ part,
                        int* __restrict__ bsum, int n) {
    __shared__ int wsum[32];
    int t = threadIdx.x;
    int i = blockIdx.x * 1024 + t;
    int v = (i < n) ? deg[i] : 0;
    int lane = t & 31, w = t >> 5;
    int x = v;
#pragma unroll
    for (int o = 1; o < 32; o <<= 1) {
        int y = __shfl_up_sync(0xffffffffu, x, o);
        if (lane >= o) x += y;
    }
    if (lane == 31) wsum[w] = x;
    __syncthreads();
    if (w == 0) {
        int s = wsum[lane];
#pragma unroll
        for (int o = 1; o < 32; o <<= 1) {
            int y = __shfl_up_sync(0xffffffffu, s, o);
            if (lane >= o) s += y;
        }
        wsum[lane] = s;
    }
    __syncthreads();
    int woff = (w > 0) ? wsum[w - 1] : 0;
    if (i < n) part[i] = x - v + woff;
    if (t == 0) bsum[blockIdx.x] = wsum[31];
}

__global__ void k_scanB(int* __restrict__ bsum, int nb) {
    __shared__ int w0tot;
    int t = threadIdx.x;
    int lane = t & 31, w = t >> 5;
    int v = (t < nb) ? bsum[t] : 0;
    int x = v;
#pragma unroll
    for (int o = 1; o < 32; o <<= 1) {
        int y = __shfl_up_sync(0xffffffffu, x, o);
        if (lane >= o) x += y;
    }
    if (w == 0 && lane == 31) w0tot = x;
    __syncthreads();
    if (w == 1) x += w0tot;
    if (t < nb) bsum[t] = x - v;
}

__global__ void k_scanC(const int* __restrict__ part, const int* __restrict__ bsum,
                        int* __restrict__ off, int* __restrict__ cur,
                        float* __restrict__ GM, float* __restrict__ GDEN,
                        int n, int etot) {
    int i = blockIdx.x * 1024 + threadIdx.x;
    if (i < n) {
        int v = part[i] + bsum[blockIdx.x];
        off[i] = v;
        cur[i] = v;
    }
    if (i == 0) off[n] = etot;
    if (blockIdx.x == 0 && threadIdx.x < GG) {
        GM[threadIdx.x] = -INFINITY;
        GDEN[threadIdx.x] = 0.f;
    }
}

__global__ void k_scatter(const int* __restrict__ ei, int* __restrict__ cur,
                          int* __restrict__ srcs, int etot, int eraw) {
    int e = blockIdx.x * blockDim.x + threadIdx.x;
    if (e >= etot) return;
    int s, d;
    if (e < eraw) { s = __ldg(&ei[e]); d = __ldg(&ei[eraw + e]); }
    else          { s = d = e - eraw; }
    int pos = atomicAdd(&cur[d], 1);
    srcs[pos] = s;
}

// ================= GEMM + fused alpha epilogue (H stored fp16) =================
template<int K, int KC>
__global__ void __launch_bounds__(384, 2) k_gemm2(const float* __restrict__ A,
                                                  const float* __restrict__ W,
                                                  const float* __restrict__ asrc,
                                                  const float* __restrict__ adst,
                                                  __half2* __restrict__ H2,
                                                  float* __restrict__ AS,
                                                  float* __restrict__ AD, int n) {
    extern __shared__ float sm[];
    float* Bs = sm;              // K*96 (full weights, global-k)
    float* As = sm + K * 96;     // KC*193
    int tid = threadIdx.x;
    int w = tid >> 5, lane = tid & 31;
    int row0 = blockIdx.x * 192;
    int head = w / 3;

    ull acc[6][4];
#pragma unroll
    for (int f = 0; f < 6; f++)
#pragma unroll
        for (int j = 0; j < 4; j++) acc[f][j] = 0ull;

    for (int i = tid; i < K * 96; i += 384) Bs[i] = W[i];

    for (int k0 = 0; k0 < K; k0 += KC) {
        __syncthreads();
        for (int i = tid; i < 192 * KC; i += 384) {
            int k = i % KC, r = i / KC;
            int row = row0 + r;
            As[k * 193 + r] = (row < n) ? A[row * K + k0 + k] : 0.f;
        }
        __syncthreads();
#pragma unroll 8
        for (int k = 0; k < KC; k++) {
            const ull* b_ = (const ull*)&Bs[(k0 + k) * 96 + w * 8];
            ull bp0 = b_[0], bp1 = b_[1], bp2 = b_[2], bp3 = b_[3];
            const float* a_ = &As[k * 193 + lane];
#pragma unroll
            for (int f = 0; f < 6; f++) {
                float av = a_[f * 32];
                ull ap = pk2(av, av);
                acc[f][0] = fma2(ap, bp0, acc[f][0]);
                acc[f][1] = fma2(ap, bp1, acc[f][1]);
                acc[f][2] = fma2(ap, bp2, acc[f][2]);
                acc[f][3] = fma2(ap, bp3, acc[f][3]);
            }
        }
    }

    float a_s[8], a_d[8];
#pragma unroll
    for (int j = 0; j < 8; j++) {
        a_s[j] = __ldg(&asrc[w * 8 + j]);
        a_d[j] = __ldg(&adst[w * 8 + j]);
    }
    float* sAl = sm;
    __syncthreads();
    for (int i = tid; i < 192 * 8; i += 384) sAl[i] = 0.f;
    __syncthreads();

#pragma unroll
    for (int f = 0; f < 6; f++) {
        int r = lane + f * 32;
        int row = row0 + r;
        float o0x, o0y, o0z, o0w, o1x, o1y, o1z, o1w;
        upk2(acc[f][0], o0x, o0y);
        upk2(acc[f][1], o0z, o0w);
        upk2(acc[f][2], o1x, o1y);
        upk2(acc[f][3], o1z, o1w);
        if (row < n) {
            union { __half2 h[4]; uint4 u; } pk;
            pk.h[0] = __floats2half2_rn(o0x, o0y);
            pk.h[1] = __floats2half2_rn(o0z, o0w);
            pk.h[2] = __floats2half2_rn(o1x, o1y);
            pk.h[3] = __floats2half2_rn(o1z, o1w);
            *(uint4*)(H2 + row * 48 + w * 4) = pk.u;
        }
        float sp = o0x * a_s[0] + o0y * a_s[1] + o0z * a_s[2] + o0w * a_s[3]
                 + o1x * a_s[4] + o1y * a_s[5] + o1z * a_s[6] + o1w * a_s[7];
        float dp = o0x * a_d[0] + o0y * a_d[1] + o0z * a_d[2] + o0w * a_d[3]
                 + o1x * a_d[4] + o1y * a_d[5] + o1z * a_d[6] + o1w * a_d[7];
        atomicAdd(&sAl[r * 8 + head], sp);
        atomicAdd(&sAl[r * 8 + 4 + head], dp);
    }
    __syncthreads();
    for (int i = tid; i < 192 * 4; i += 384) {
        int r = i >> 2, hh = i & 3;
        int row = row0 + r;
        if (row < n) {
            AS[row * 4 + hh] = sAl[r * 8 + hh];
            AD[row * 4 + hh] = sAl[r * 8 + 4 + hh];
        }
    }
}

// ================= fused softmax + aggregation (warp per dst, fp16 H gather) =================
#define DCAP 128
__global__ void k_sagg(const int* __restrict__ off, const int* __restrict__ srcs,
                       const float* __restrict__ AS, const float* __restrict__ AD,
                       const __half2* __restrict__ H2, const float* __restrict__ bias,
                       float* __restrict__ OUT, int n) {
    __shared__ int    ssrc[8][DCAP];
    __shared__ float4 slog[8][DCAP];
    int gtid = blockIdx.x * blockDim.x + threadIdx.x;
    int node = gtid >> 5, lane = gtid & 31;
    int ws = threadIdx.x >> 5;
    if (node >= n) return;
    int beg = __ldg(&off[node]), end = __ldg(&off[node + 1]);
    int deg = end - beg;
    float4 ad = *(const float4*)(AD + node * 4);

    bool act = lane < 24;
    int head = lane / 6;
    float4 acc = make_float4(0.f, 0.f, 0.f, 0.f);
    float4 den = make_float4(0.f, 0.f, 0.f, 0.f);
    float4 mx = make_float4(-INFINITY, -INFINITY, -INFINITY, -INFINITY);

    if (deg <= DCAP) {
        for (int j = lane; j < deg; j += 32) {
            int s = __ldg(&srcs[beg + j]);
            float4 a = *(const float4*)(AS + s * 4);
            float t; float4 v;
            t = a.x + ad.x; v.x = t > 0.f ? t : 0.2f * t; mx.x = fmaxf(mx.x, v.x);
            t = a.y + ad.y; v.y = t > 0.f ? t : 0.2f * t; mx.y = fmaxf(mx.y, v.y);
            t = a.z + ad.z; v.z = t > 0.f ? t : 0.2f * t; mx.z = fmaxf(mx.z, v.z);
            t = a.w + ad.w; v.w = t > 0.f ? t : 0.2f * t; mx.w = fmaxf(mx.w, v.w);
            ssrc[ws][j] = s;
            slog[ws][j] = v;
        }
#pragma unroll
        for (int o = 16; o > 0; o >>= 1) {
            mx.x = fmaxf(mx.x, __shfl_xor_sync(0xffffffffu, mx.x, o));
            mx.y = fmaxf(mx.y, __shfl_xor_sync(0xffffffffu, mx.y, o));
            mx.z = fmaxf(mx.z, __shfl_xor_sync(0xffffffffu, mx.z, o));
            mx.w = fmaxf(mx.w, __shfl_xor_sync(0xffffffffu, mx.w, o));
        }
        __syncwarp();
        for (int j = lane; j < deg; j += 32) {
            float4 v = slog[ws][j];
            float4 ex;
            ex.x = __expf(v.x - mx.x); ex.y = __expf(v.y - mx.y);
            ex.z = __expf(v.z - mx.z); ex.w = __expf(v.w - mx.w);
            slog[ws][j] = ex;
            den.x += ex.x; den.y += ex.y; den.z += ex.z; den.w += ex.w;
        }
        __syncwarp();
        if (act) {
            const float* sexf = (const float*)&slog[ws][0];
#pragma unroll 4
            for (int j = 0; j < deg; j++) {
                int s = ssrc[ws][j];
                float wv = sexf[j * 4 + head];
                uint2 raw = __ldg((const uint2*)(H2 + s * 48) + lane);
                float2 f01 = __half22float2(*(__half2*)&raw.x);
                float2 f23 = __half22float2(*(__half2*)&raw.y);
                acc.x = fmaf(f01.x, wv, acc.x);
                acc.y = fmaf(f01.y, wv, acc.y);
                acc.z = fmaf(f23.x, wv, acc.z);
                acc.w = fmaf(f23.y, wv, acc.w);
            }
        }
    } else {
        for (int e = beg + lane; e < end; e += 32) {
            int s = __ldg(&srcs[e]);
            float4 a = *(const float4*)(AS + s * 4);
            float t;
            t = a.x + ad.x; t = t > 0.f ? t : 0.2f * t; mx.x = fmaxf(mx.x, t);
            t = a.y + ad.y; t = t > 0.f ? t : 0.2f * t; mx.y = fmaxf(mx.y, t);
            t = a.z + ad.z; t = t > 0.f ? t : 0.2f * t; mx.z = fmaxf(mx.z, t);
            t = a.w + ad.w; t = t > 0.f ? t : 0.2f * t; mx.w = fmaxf(mx.w, t);
        }
#pragma unroll
        for (int o = 16; o > 0; o >>= 1) {
            mx.x = fmaxf(mx.x, __shfl_xor_sync(0xffffffffu, mx.x, o));
            mx.y = fmaxf(mx.y, __shfl_xor_sync(0xffffffffu, mx.y, o));
            mx.z = fmaxf(mx.z, __shfl_xor_sync(0xffffffffu, mx.z, o));
            mx.w = fmaxf(mx.w, __shfl_xor_sync(0xffffffffu, mx.w, o));
        }
        for (int c0 = beg; c0 < end; c0 += 32) {
            int e = c0 + lane;
            if (e < end) {
                int s = __ldg(&srcs[e]);
                float4 a = *(const float4*)(AS + s * 4);
                float t; float4 ex;
                t = a.x + ad.x; t = t > 0.f ? t : 0.2f * t; ex.x = __expf(t - mx.x);
                t = a.y + ad.y; t = t > 0.f ? t : 0.2f * t; ex.y = __expf(t - mx.y);
                t = a.z + ad.z; t = t > 0.f ? t : 0.2f * t; ex.z = __expf(t - mx.z);
                t = a.w + ad.w; t = t > 0.f ? t : 0.2f * t; ex.w = __expf(t - mx.w);
                den.x += ex.x; den.y += ex.y; den.z += ex.z; den.w += ex.w;
                ssrc[ws][lane] = s;
                slog[ws][lane] = ex;
            }
            __syncwarp();
            int cnt = min(32, end - c0);
            if (act) {
                const float* sexf = (const float*)&slog[ws][0];
                for (int j = 0; j < cnt; j++) {
                    int s = ssrc[ws][j];
                    float wv = sexf[j * 4 + head];
                    uint2 raw = __ldg((const uint2*)(H2 + s * 48) + lane);
                    float2 f01 = __half22float2(*(__half2*)&raw.x);
                    float2 f23 = __half22float2(*(__half2*)&raw.y);
                    acc.x = fmaf(f01.x, wv, acc.x);
                    acc.y = fmaf(f01.y, wv, acc.y);
                    acc.z = fmaf(f23.x, wv, acc.z);
                    acc.w = fmaf(f23.y, wv, acc.w);
                }
            }
            __syncwarp();
        }
    }

#pragma unroll
    for (int o = 16; o > 0; o >>= 1) {
        den.x += __shfl_xor_sync(0xffffffffu, den.x, o);
        den.y += __shfl_xor_sync(0xffffffffu, den.y, o);
        den.z += __shfl_xor_sync(0xffffffffu, den.z, o);
        den.w += __shfl_xor_sync(0xffffffffu, den.w, o);
    }
    if (act) {
        float dh = head == 0 ? den.x : (head == 1 ? den.y : (head == 2 ? den.z : den.w));
        float inv = 1.f / (dh + 1e-16f);
        float4 b4 = *(const float4*)(bias + lane * 4);
        float4 o;
        o.x = acc.x * inv + b4.x;  o.x = o.x > 0.f ? o.x : expm1f(o.x);
        o.y = acc.y * inv + b4.y;  o.y = o.y > 0.f ? o.y : expm1f(o.y);
        o.z = acc.z * inv + b4.z;  o.z = o.z > 0.f ? o.z : expm1f(o.z);
        o.w = acc.w * inv + b4.w;  o.w = o.w > 0.f ? o.w : expm1f(o.w);
        *(float4*)(OUT + node * 96 + lane * 4) = o;
    }
}

// ================= gate MLP as GEMM: [n,96]@[96,48] -> relu -> ·gw2 =================
// 192-row tile, 384 threads, warp w owns hidden cols [w*4, w*4+4), lane owns rows lane+32f.
__global__ void __launch_bounds__(384, 2) k_gateg(const float* __restrict__ O,
                                                  const float* __restrict__ gw1,
                                                  const float* __restrict__ gb1,
                                                  const float* __restrict__ gw2,
                                                  const float* __restrict__ gb2,
                                                  const int* __restrict__ batch,
                                                  float* __restrict__ GATE,
                                                  float* __restrict__ GM, int n) {
    extern __shared__ float sm[];
    float* Bs = sm;              // 96*48
    float* As = sm + 96 * 48;    // 96*193
    int tid = threadIdx.x;
    int w = tid >> 5, lane = tid & 31;
    int row0 = blockIdx.x * 192;

    ull acc[6][2];
#pragma unroll
    for (int f = 0; f < 6; f++) { acc[f][0] = 0ull; acc[f][1] = 0ull; }

    for (int i = tid; i < 96 * 48; i += 384) Bs[i] = gw1[i];
    for (int i = tid; i < 192 * 96; i += 384) {
        int k = i % 96, r = i / 96;
        int row = row0 + r;
        As[k * 193 + r] = (row < n) ? O[row * 96 + k] : 0.f;
    }
    __syncthreads();

#pragma unroll 8
    for (int k = 0; k < 96; k++) {
        const ull* b_ = (const ull*)&Bs[k * 48 + w * 4];
        ull bp0 = b_[0], bp1 = b_[1];
        const float* a_ = &As[k * 193 + lane];
#pragma unroll
        for (int f = 0; f < 6; f++) {
            float av = a_[f * 32];
            ull ap = pk2(av, av);
            acc[f][0] = fma2(ap, bp0, acc[f][0]);
            acc[f][1] = fma2(ap, bp1, acc[f][1]);
        }
    }

    // epilogue: relu(h + gb1)·gw2, reduce 12 warp-partials per row in smem
    float b1v[4], g2v[4];
#pragma unroll
    for (int jj = 0; jj < 4; jj++) {
        b1v[jj] = __ldg(&gb1[w * 4 + jj]);
        g2v[jj] = __ldg(&gw2[w * 4 + jj]);
    }
    float* sAl = sm;            // reuse: 192 floats
    __syncthreads();
    for (int i = tid; i < 192; i += 384) sAl[i] = 0.f;
    __syncthreads();

#pragma unroll
    for (int f = 0; f < 6; f++) {
        int r = lane + f * 32;
        float h0, h1, h2, h3;
        upk2(acc[f][0], h0, h1);
        upk2(acc[f][1], h2, h3);
        float p = fmaxf(h0 + b1v[0], 0.f) * g2v[0]
                + fmaxf(h1 + b1v[1], 0.f) * g2v[1]
                + fmaxf(h2 + b1v[2], 0.f) * g2v[2]
                + fmaxf(h3 + b1v[3], 0.f) * g2v[3];
        atomicAdd(&sAl[r], p);
    }
    __syncthreads();
    float gb2v = __ldg(&gb2[0]);
    for (int i = tid; i < 192; i += 384) {
        int row = row0 + i;
        if (row < n) {
            float g = sAl[i] + gb2v;
            GATE[row] = g;
            atomicMaxF(&GM[__ldg(&batch[row])], g);
        }
    }
}

__global__ void k_gate_exp(const float* __restrict__ GATE, const float* __restrict__ GM,
                           const int* __restrict__ batch, float* __restrict__ GE,
                           float* __restrict__ GDEN, int n) {
    __shared__ float sden[GG];
    for (int i = threadIdx.x; i < GG; i += blockDim.x) sden[i] = 0.f;
    __syncthreads();
    int i = blockIdx.x * blockDim.x + threadIdx.x;
    if (i < n) {
        int b = batch[i];
        float m = GM[b];
        if (m == -INFINITY) m = 0.f;
        float e = __expf(GATE[i] - m);
        GE[i] = e;
        atomicAdd(&sden[b], e);
    }
    __syncthreads();
    for (int i2 = threadIdx.x; i2 < GG; i2 += blockDim.x)
        if (sden[i2] != 0.f) atomicAdd(&GDEN[i2], sden[i2]);
}

// ================= pooling: 8 blocks per graph -> disjoint partials =================
__global__ void k_pool2(const float* __restrict__ H, const float* __restrict__ GE,
                        const float* __restrict__ GDEN, const int* __restrict__ batch,
                        float* __restrict__ POOL, int n) {
    __shared__ float red[192];
    int g = blockIdx.x;
    int part = blockIdx.y;
    int tid = threadIdx.x;
    int lo = 0, hi = n;
    while (lo < hi) { int mid = (lo + hi) >> 1; if (__ldg(&batch[mid]) < g) lo = mid + 1; else hi = mid; }
    int beg = lo;
    lo = beg; hi = n;
    while (lo < hi) { int mid = (lo + hi) >> 1; if (__ldg(&batch[mid]) < g + 1) lo = mid + 1; else hi = mid; }
    int end = lo;

    float invden = 1.f / (GDEN[g] + 1e-16f);
    int half = tid / 96, c = tid - half * 96;
    float acc = 0.f;
    for (int node = beg + part * 2 + half; node < end; node += 16) {
        float wv = __ldg(&GE[node]) * invden;
        acc = fmaf(__ldg(&H[node * 96 + c]), wv, acc);
    }
    red[tid] = acc;
    __syncthreads();
    if (tid < 96) POOL[(g * 8 + part) * 96 + tid] = red[tid] + red[tid + 96];
}

__global__ void k_final(const float* __restrict__ POOL, const float* __restrict__ fw1,
                        const float* __restrict__ fb1, const float* __restrict__ fw2,
                        const float* __restrict__ fb2, float* __restrict__ out) {
    __shared__ float pr[96];
    __shared__ float hid[96];
    int g = blockIdx.x, j = threadIdx.x;
    float p = 0.f;
#pragma unroll
    for (int q = 0; q < 8; q++) p += POOL[(g * 8 + q) * 96 + j];
    pr[j] = p;
    __syncthreads();
    float a = fb1[j];
#pragma unroll 8
    for (int k = 0; k < 96; k++) a += pr[k] * fw1[k * 96 + j];
    hid[j] = fmaxf(a, 0.f);
    __syncthreads();
    if (j < 3) {
        float o = fb2[j];
        for (int k = 0; k < 96; k++) o += hid[k] * fw2[k * 3 + j];
        out[g * 3 + j] = o;
    }
}

// ================= host =================
extern "C" void kernel_launch(void* const* d_in, const int* in_sizes, int n_in,
                              void* d_out, int out_size) {
    const float* x     = (const float*)d_in[0];
    const int*   ei    = (const int*)d_in[1];
    const int*   batch = (const int*)d_in[2];
    int idx = 3;
    if (n_in > 3 && in_sizes[3] == 1) idx = 4;
    const float* W1  = (const float*)d_in[idx++];
    const float* as1 = (const float*)d_in[idx++];
    const float* ad1 = (const float*)d_in[idx++];
    const float* b1  = (const float*)d_in[idx++];
    const float* W2  = (const float*)d_in[idx++];
    const float* as2 = (const float*)d_in[idx++];
    const float* ad2 = (const float*)d_in[idx++];
    const float* b2  = (const float*)d_in[idx++];
    const float* gw1 = (const float*)d_in[idx++];
    const float* gb1 = (const float*)d_in[idx++];
    const float* gw2 = (const float*)d_in[idx++];
    const float* gb2 = (const float*)d_in[idx++];
    const float* fw1 = (const float*)d_in[idx++];
    const float* fb1 = (const float*)d_in[idx++];
    const float* fw2 = (const float*)d_in[idx++];
    const float* fb2 = (const float*)d_in[idx++];

    int n    = in_sizes[0] / 128;
    int eraw = in_sizes[1] / 2;
    int etot = eraw + n;

    float *o, *as_, *ad_, *gate, *ge, *gm, *gden, *pool;
    __half2* h2;
    int *deg, *part, *bsum, *off, *srcs;
    cudaGetSymbolAddress((void**)&h2,   d_h2);
    cudaGetSymbolAddress((void**)&o,    d_o);
    cudaGetSymbolAddress((void**)&as_,  d_as);
    cudaGetSymbolAddress((void**)&ad_,  d_ad);
    cudaGetSymbolAddress((void**)&gate, d_gate);
    cudaGetSymbolAddress((void**)&ge,   d_ge);
    cudaGetSymbolAddress((void**)&gm,   d_gm);
    cudaGetSymbolAddress((void**)&gden, d_gden);
    cudaGetSymbolAddress((void**)&pool, d_pool);
    cudaGetSymbolAddress((void**)&deg,  d_deg);
    cudaGetSymbolAddress((void**)&part, d_part);
    cudaGetSymbolAddress((void**)&bsum, d_bsum);
    cudaGetSymbolAddress((void**)&off,  d_off);
    cudaGetSymbolAddress((void**)&srcs, d_srcs);

    int smem1 = (128 * 96 + 64 * 193) * 4;
    int smem2 = (96 * 96 + 96 * 193) * 4;
    int smemG = (96 * 48 + 96 * 193) * 4;
    cudaFuncSetAttribute(k_gemm2<128, 64>, cudaFuncAttributeMaxDynamicSharedMemorySize, smem1);
    cudaFuncSetAttribute(k_gemm2<96, 96>,  cudaFuncAttributeMaxDynamicSharedMemorySize, smem2);
    cudaFuncSetAttribute(k_gateg,          cudaFuncAttributeMaxDynamicSharedMemorySize, smemG);

    int gEdge  = (etot + 255) / 256;
    int gWarp  = (n * 32 + 255) / 256;
    int gGemm  = (n + 191) / 192;
    int gNode  = (n + 255) / 256;
    int gScan  = (n + 1023) / 1024;

    // side stream + events (created once, outside any graph capture)
    static cudaStream_t s1 = nullptr;
    static cudaEvent_t evFork = nullptr, evJoin = nullptr;
    if (s1 == nullptr) {
        cudaStreamCreateWithFlags(&s1, cudaStreamNonBlocking);
        cudaEventCreateWithFlags(&evFork, cudaEventDisableTiming);
        cudaEventCreateWithFlags(&evJoin, cudaEventDisableTiming);
    }

    // ---- fork: CSR build on side stream, layer-1 GEMM on main stream ----
    cudaEventRecord(evFork, 0);
    cudaStreamWaitEvent(s1, evFork, 0);

    cudaMemsetAsync(deg, 0, n * sizeof(int), s1);
    k_hist<<<gEdge, 256, 0, s1>>>(ei, deg, etot, eraw);
    k_scanA<<<gScan, 1024, 0, s1>>>(deg, part, bsum, n);
    k_scanB<<<1, 64, 0, s1>>>(bsum, gScan);
    k_scanC<<<gScan, 1024, 0, s1>>>(part, bsum, off, deg, gm, gden, n, etot);
    k_scatter<<<gEdge, 256, 0, s1>>>(ei, deg, srcs, etot, eraw);
    cudaEventRecord(evJoin, s1);

    k_gemm2<128, 64><<<gGemm, 384, smem1>>>(x, W1, as1, ad1, h2, as_, ad_, n);

    // ---- join, then edge phase ----
    cudaStreamWaitEvent(0, evJoin, 0);
    k_sagg<<<gWarp, 256>>>(off, srcs, as_, ad_, h2, b1, o, n);

    // ---- layer 2 ----
    k_gemm2<96, 96><<<gGemm, 384, smem2>>>(o, W2, as2, ad2, h2, as_, ad_, n);
    k_sagg<<<gWarp, 256>>>(off, srcs, as_, ad_, h2, b2, o, n);

    // ---- global attention pool + final MLP ----
    k_gateg<<<gGemm, 384, smemG>>>(o, gw1, gb1, gw2, gb2, batch, gate, gm, n);
    k_gate_exp<<<gNode, 256>>>(gate, gm, batch, ge, gden, n);
    k_pool2<<<dim3(GG, 8), 192>>>(o, ge, gden, batch, pool, n);
    k_final<<<GG, 96>>>(pool, fw1, fb1, fw2, fb2, (float*)d_out);
}

// round 12
// speedup vs baseline: 1.2246x; 1.0005x over previous
#include <cuda_runtime.h>
#include <cuda_fp16.h>
#include <math.h>

#define NN 50000
#define EE 800000
#define ETOT (EE + NN)
#define GG 64

// ---------------- scratch ----------------
__device__ __half2 d_h2[NN * 48];   // fp16 message matrix (H), 48 half2 per row
__device__ float d_o[NN * 96];
__device__ float d_as[NN * 4];
__device__ float d_ad[NN * 4];
__device__ int   d_deg[NN];
__device__ int   d_part[NN];
__device__ int   d_bsum[64];
__device__ int   d_off[NN + 1];
__device__ int   d_srcs[ETOT];
__device__ float d_gate[NN];
__device__ float d_gm[GG];
__device__ float d_gden[GG];
__device__ float d_pool[GG * 8 * 96];

__device__ __forceinline__ void atomicMaxF(float* a, float v) {
    if (v >= 0.f) atomicMax((int*)a, __float_as_int(v));
    else          atomicMin((unsigned int*)a, __float_as_uint(v));
}

typedef unsigned long long ull;
__device__ __forceinline__ ull pk2(float x, float y) {
    ull r;
    asm("mov.b64 %0, {%1, %2};" : "=l"(r) : "f"(x), "f"(y));
    return r;
}
__device__ __forceinline__ ull fma2(ull a, ull b, ull c) {
    ull d;
    asm("fma.rn.f32x2 %0, %1, %2, %3;" : "=l"(d) : "l"(a), "l"(b), "l"(c));
    return d;
}
__device__ __forceinline__ void upk2(ull v, float& x, float& y) {
    asm("mov.b64 {%0, %1}, %2;" : "=f"(x), "=f"(y) : "l"(v));
}

// ================= CSR build =================
__global__ void k_hist(const int* __restrict__ ei, int* __restrict__ deg, int etot, int eraw) {
    int e = blockIdx.x * blockDim.x + threadIdx.x;
    if (e >= etot) return;
    int d = (e < eraw) ? __ldg(&ei[eraw + e]) : e - eraw;
    atomicAdd(&deg[d], 1);
}

__global__ void k_scanA(const int* __restrict__ deg, int* __restrict__ part,
                        int* __restrict__ bsum, int n) {
    __shared__ int wsum[32];
    int t = threadIdx.x;
    int i = blockIdx.x * 1024 + t;
    int v = (i < n) ? deg[i] : 0;
    int lane = t & 31, w = t >> 5;
    int x = v;
#pragma unroll
    for (int o = 1; o < 32; o <<= 1) {
        int y = __shfl_up_sync(0xffffffffu, x, o);
        if (lane >= o) x += y;
    }
    if (lane == 31) wsum[w] = x;
    __syncthreads();
    if (w == 0) {
        int s = wsum[lane];
#pragma unroll
        for (int o = 1; o < 32; o <<= 1) {
            int y = __shfl_up_sync(0xffffffffu, s, o);
            if (lane >= o) s += y;
        }
        wsum[lane] = s;
    }
    __syncthreads();
    int woff = (w > 0) ? wsum[w - 1] : 0;
    if (i < n) part[i] = x - v + woff;
    if (t == 0) bsum[blockIdx.x] = wsum[31];
}

__global__ void k_scanB(int* __restrict__ bsum, int nb) {
    __shared__ int w0tot;
    int t = threadIdx.x;
    int lane = t & 31, w = t >> 5;
    int v = (t < nb) ? bsum[t] : 0;
    int x = v;
#pragma unroll
    for (int o = 1; o < 32; o <<= 1) {
        int y = __shfl_up_sync(0xffffffffu, x, o);
        if (lane >= o) x += y;
    }
    if (w == 0 && lane == 31) w0tot = x;
    __syncthreads();
    if (w == 1) x += w0tot;
    if (t < nb) bsum[t] = x - v;
}

__global__ void k_scanC(const int* __restrict__ part, const int* __restrict__ bsum,
                        int* __restrict__ off, int* __restrict__ cur,
                        float* __restrict__ GM, float* __restrict__ GDEN,
                        int n, int etot) {
    int i = blockIdx.x * 1024 + threadIdx.x;
    if (i < n) {
        int v = part[i] + bsum[blockIdx.x];
        off[i] = v;
        cur[i] = v;
    }
    if (i == 0) off[n] = etot;
    if (blockIdx.x == 0 && threadIdx.x < GG) {
        GM[threadIdx.x] = -INFINITY;
        GDEN[threadIdx.x] = 0.f;
    }
}

__global__ void k_scatter(const int* __restrict__ ei, int* __restrict__ cur,
                          int* __restrict__ srcs, int etot, int eraw) {
    int e = blockIdx.x * blockDim.x + threadIdx.x;
    if (e >= etot) return;
    int s, d;
    if (e < eraw) { s = __ldg(&ei[e]); d = __ldg(&ei[eraw + e]); }
    else          { s = d = e - eraw; }
    int pos = atomicAdd(&cur[d], 1);
    srcs[pos] = s;
}

// ================= GEMM + fused alpha epilogue (fp16 A staging, fp16 H out) =================
// TM=192, 384 thr, 2 blocks/SM. warp w owns cols [w*8,w*8+8); lane owns rows lane*6+f (f=0..5).
// A staged as half with stride 194 (even -> LDS.32 aligned; banks (k+3*lane)%32 conflict-free).
template<int K, int KC>
__global__ void __launch_bounds__(384, 2) k_gemm2(const float* __restrict__ A,
                                                  const float* __restrict__ W,
                                                  const float* __restrict__ asrc,
                                                  const float* __restrict__ adst,
                                                  __half2* __restrict__ H2,
                                                  float* __restrict__ AS,
                                                  float* __restrict__ AD, int n) {
    extern __shared__ float sm[];
    float* Bs = sm;                            // K*96 fp32 (full weights, global-k)
    __half* Ah = (__half*)(sm + K * 96);       // KC*194 halfs
    int tid = threadIdx.x;
    int w = tid >> 5, lane = tid & 31;
    int row0 = blockIdx.x * 192;
    int head = w / 3;

    ull acc[6][4];
#pragma unroll
    for (int f = 0; f < 6; f++)
#pragma unroll
        for (int j = 0; j < 4; j++) acc[f][j] = 0ull;

    for (int i = tid; i < K * 96; i += 384) Bs[i] = W[i];

    for (int k0 = 0; k0 < K; k0 += KC) {
        __syncthreads();
        for (int i = tid; i < 192 * KC; i += 384) {
            int k = i % KC, r = i / KC;      // consecutive tid -> consecutive k (coalesced LDG, conflict-free STS)
            int row = row0 + r;
            Ah[k * 194 + r] = (row < n) ? __float2half(A[row * K + k0 + k]) : __half(0.f);
        }
        __syncthreads();
#pragma unroll 8
        for (int k = 0; k < KC; k++) {
            const ull* b_ = (const ull*)&Bs[(k0 + k) * 96 + w * 8];
            ull bp0 = b_[0], bp1 = b_[1], bp2 = b_[2], bp3 = b_[3];
            const __half2* a_ = (const __half2*)(Ah + k * 194 + lane * 6);
            float2 f01 = __half22float2(a_[0]);
            float2 f23 = __half22float2(a_[1]);
            float2 f45 = __half22float2(a_[2]);
            float av[6] = { f01.x, f01.y, f23.x, f23.y, f45.x, f45.y };
#pragma unroll
            for (int f = 0; f < 6; f++) {
                ull ap = pk2(av[f], av[f]);
                acc[f][0] = fma2(ap, bp0, acc[f][0]);
                acc[f][1] = fma2(ap, bp1, acc[f][1]);
                acc[f][2] = fma2(ap, bp2, acc[f][2]);
                acc[f][3] = fma2(ap, bp3, acc[f][3]);
            }
        }
    }

    float a_s[8], a_d[8];
#pragma unroll
    for (int j = 0; j < 8; j++) {
        a_s[j] = __ldg(&asrc[w * 8 + j]);
        a_d[j] = __ldg(&adst[w * 8 + j]);
    }
    float* sAl = sm;
    __syncthreads();
    for (int i = tid; i < 192 * 8; i += 384) sAl[i] = 0.f;
    __syncthreads();

#pragma unroll
    for (int f = 0; f < 6; f++) {
        int r = lane * 6 + f;                // contiguous-row ownership
        int row = row0 + r;
        float o0x, o0y, o0z, o0w, o1x, o1y, o1z, o1w;
        upk2(acc[f][0], o0x, o0y);
        upk2(acc[f][1], o0z, o0w);
        upk2(acc[f][2], o1x, o1y);
        upk2(acc[f][3], o1z, o1w);
        if (row < n) {
            union { __half2 h[4]; uint4 u; } pk;
            pk.h[0] = __floats2half2_rn(o0x, o0y);
            pk.h[1] = __floats2half2_rn(o0z, o0w);
            pk.h[2] = __floats2half2_rn(o1x, o1y);
            pk.h[3] = __floats2half2_rn(o1z, o1w);
            *(uint4*)(H2 + row * 48 + w * 4) = pk.u;
        }
        float sp = o0x * a_s[0] + o0y * a_s[1] + o0z * a_s[2] + o0w * a_s[3]
                 + o1x * a_s[4] + o1y * a_s[5] + o1z * a_s[6] + o1w * a_s[7];
        float dp = o0x * a_d[0] + o0y * a_d[1] + o0z * a_d[2] + o0w * a_d[3]
                 + o1x * a_d[4] + o1y * a_d[5] + o1z * a_d[6] + o1w * a_d[7];
        atomicAdd(&sAl[r * 8 + head], sp);
        atomicAdd(&sAl[r * 8 + 4 + head], dp);
    }
    __syncthreads();
    for (int i = tid; i < 192 * 4; i += 384) {
        int r = i >> 2, hh = i & 3;
        int row = row0 + r;
        if (row < n) {
            AS[row * 4 + hh] = sAl[r * 8 + hh];
            AD[row * 4 + hh] = sAl[r * 8 + 4 + hh];
        }
    }
}

// ================= fused softmax + aggregation (warp per dst, fp16 H gather) =================
#define DCAP 128
__global__ void k_sagg(const int* __restrict__ off, const int* __restrict__ srcs,
                       const float* __restrict__ AS, const float* __restrict__ AD,
                       const __half2* __restrict__ H2, const float* __restrict__ bias,
                       float* __restrict__ OUT, int n) {
    __shared__ int    ssrc[8][DCAP];
    __shared__ float4 slog[8][DCAP];
    int gtid = blockIdx.x * blockDim.x + threadIdx.x;
    int node = gtid >> 5, lane = gtid & 31;
    int ws = threadIdx.x >> 5;
    if (node >= n) return;
    int beg = __ldg(&off[node]), end = __ldg(&off[node + 1]);
    int deg = end - beg;
    float4 ad = *(const float4*)(AD + node * 4);

    bool act = lane < 24;
    int head = lane / 6;
    float4 acc = make_float4(0.f, 0.f, 0.f, 0.f);
    float4 den = make_float4(0.f, 0.f, 0.f, 0.f);
    float4 mx = make_float4(-INFINITY, -INFINITY, -INFINITY, -INFINITY);

    if (deg <= DCAP) {
        for (int j = lane; j < deg; j += 32) {
            int s = __ldg(&srcs[beg + j]);
            float4 a = *(const float4*)(AS + s * 4);
            float t; float4 v;
            t = a.x + ad.x; v.x = t > 0.f ? t : 0.2f * t; mx.x = fmaxf(mx.x, v.x);
            t = a.y + ad.y; v.y = t > 0.f ? t : 0.2f * t; mx.y = fmaxf(mx.y, v.y);
            t = a.z + ad.z; v.z = t > 0.f ? t : 0.2f * t; mx.z = fmaxf(mx.z, v.z);
            t = a.w + ad.w; v.w = t > 0.f ? t : 0.2f * t; mx.w = fmaxf(mx.w, v.w);
            ssrc[ws][j] = s;
            slog[ws][j] = v;
        }
#pragma unroll
        for (int o = 16; o > 0; o >>= 1) {
            mx.x = fmaxf(mx.x, __shfl_xor_sync(0xffffffffu, mx.x, o));
            mx.y = fmaxf(mx.y, __shfl_xor_sync(0xffffffffu, mx.y, o));
            mx.z = fmaxf(mx.z, __shfl_xor_sync(0xffffffffu, mx.z, o));
            mx.w = fmaxf(mx.w, __shfl_xor_sync(0xffffffffu, mx.w, o));
        }
        __syncwarp();
        for (int j = lane; j < deg; j += 32) {
            float4 v = slog[ws][j];
            float4 ex;
            ex.x = __expf(v.x - mx.x); ex.y = __expf(v.y - mx.y);
            ex.z = __expf(v.z - mx.z); ex.w = __expf(v.w - mx.w);
            slog[ws][j] = ex;
            den.x += ex.x; den.y += ex.y; den.z += ex.z; den.w += ex.w;
        }
        __syncwarp();
        if (act) {
            const float* sexf = (const float*)&slog[ws][0];
#pragma unroll 4
            for (int j = 0; j < deg; j++) {
                int s = ssrc[ws][j];
                float wv = sexf[j * 4 + head];
                uint2 raw = __ldg((const uint2*)(H2 + s * 48) + lane);
                float2 f01 = __half22float2(*(__half2*)&raw.x);
                float2 f23 = __half22float2(*(__half2*)&raw.y);
                acc.x = fmaf(f01.x, wv, acc.x);
                acc.y = fmaf(f01.y, wv, acc.y);
                acc.z = fmaf(f23.x, wv, acc.z);
                acc.w = fmaf(f23.y, wv, acc.w);
            }
        }
    } else {
        for (int e = beg + lane; e < end; e += 32) {
            int s = __ldg(&srcs[e]);
            float4 a = *(const float4*)(AS + s * 4);
            float t;
            t = a.x + ad.x; t = t > 0.f ? t : 0.2f * t; mx.x = fmaxf(mx.x, t);
            t = a.y + ad.y; t = t > 0.f ? t : 0.2f * t; mx.y = fmaxf(mx.y, t);
            t = a.z + ad.z; t = t > 0.f ? t : 0.2f * t; mx.z = fmaxf(mx.z, t);
            t = a.w + ad.w; t = t > 0.f ? t : 0.2f * t; mx.w = fmaxf(mx.w, t);
        }
#pragma unroll
        for (int o = 16; o > 0; o >>= 1) {
            mx.x = fmaxf(mx.x, __shfl_xor_sync(0xffffffffu, mx.x, o));
            mx.y = fmaxf(mx.y, __shfl_xor_sync(0xffffffffu, mx.y, o));
            mx.z = fmaxf(mx.z, __shfl_xor_sync(0xffffffffu, mx.z, o));
            mx.w = fmaxf(mx.w, __shfl_xor_sync(0xffffffffu, mx.w, o));
        }
        for (int c0 = beg; c0 < end; c0 += 32) {
            int e = c0 + lane;
            if (e < end) {
                int s = __ldg(&srcs[e]);
                float4 a = *(const float4*)(AS + s * 4);
                float t; float4 ex;
                t = a.x + ad.x; t = t > 0.f ? t : 0.2f * t; ex.x = __expf(t - mx.x);
                t = a.y + ad.y; t = t > 0.f ? t : 0.2f * t; ex.y = __expf(t - mx.y);
                t = a.z + ad.z; t = t > 0.f ? t : 0.2f * t; ex.z = __expf(t - mx.z);
                t = a.w + ad.w; t = t > 0.f ? t : 0.2f * t; ex.w = __expf(t - mx.w);
                den.x += ex.x; den.y += ex.y; den.z += ex.z; den.w += ex.w;
                ssrc[ws][lane] = s;
                slog[ws][lane] = ex;
            }
            __syncwarp();
            int cnt = min(32, end - c0);
            if (act) {
                const float* sexf = (const float*)&slog[ws][0];
                for (int j = 0; j < cnt; j++) {
                    int s = ssrc[ws][j];
                    float wv = sexf[j * 4 + head];
                    uint2 raw = __ldg((const uint2*)(H2 + s * 48) + lane);
                    float2 f01 = __half22float2(*(__half2*)&raw.x);
                    float2 f23 = __half22float2(*(__half2*)&raw.y);
                    acc.x = fmaf(f01.x, wv, acc.x);
                    acc.y = fmaf(f01.y, wv, acc.y);
                    acc.z = fmaf(f23.x, wv, acc.z);
                    acc.w = fmaf(f23.y, wv, acc.w);
                }
            }
            __syncwarp();
        }
    }

#pragma unroll
    for (int o = 16; o > 0; o >>= 1) {
        den.x += __shfl_xor_sync(0xffffffffu, den.x, o);
        den.y += __shfl_xor_sync(0xffffffffu, den.y, o);
        den.z += __shfl_xor_sync(0xffffffffu, den.z, o);
        den.w += __shfl_xor_sync(0xffffffffu, den.w, o);
    }
    if (act) {
        float dh = head == 0 ? den.x : (head == 1 ? den.y : (head == 2 ? den.z : den.w));
        float inv = 1.f / (dh + 1e-16f);
        float4 b4 = *(const float4*)(bias + lane * 4);
        float4 o;
        o.x = acc.x * inv + b4.x;  o.x = o.x > 0.f ? o.x : expm1f(o.x);
        o.y = acc.y * inv + b4.y;  o.y = o.y > 0.f ? o.y : expm1f(o.y);
        o.z = acc.z * inv + b4.z;  o.z = o.z > 0.f ? o.z : expm1f(o.z);
        o.w = acc.w * inv + b4.w;  o.w = o.w > 0.f ? o.w : expm1f(o.w);
        *(float4*)(OUT + node * 96 + lane * 4) = o;
    }
}

// ================= gate MLP as GEMM: [n,96]@[96,48] -> relu -> ·gw2 =================
__global__ void __launch_bounds__(384, 2) k_gateg(const float* __restrict__ O,
                                                  const float* __restrict__ gw1,
                                                  const float* __restrict__ gb1,
                                                  const float* __restrict__ gw2,
                                                  const float* __restrict__ gb2,
                                                  const int* __restrict__ batch,
                                                  float* __restrict__ GATE,
                                                  float* __restrict__ GM, int n) {
    extern __shared__ float sm[];
    float* Bs = sm;              // 96*48
    float* As = sm + 96 * 48;    // 96*193
    int tid = threadIdx.x;
    int w = tid >> 5, lane = tid & 31;
    int row0 = blockIdx.x * 192;

    ull acc[6][2];
#pragma unroll
    for (int f = 0; f < 6; f++) { acc[f][0] = 0ull; acc[f][1] = 0ull; }

    for (int i = tid; i < 96 * 48; i += 384) Bs[i] = gw1[i];
    for (int i = tid; i < 192 * 96; i += 384) {
        int k = i % 96, r = i / 96;
        int row = row0 + r;
        As[k * 193 + r] = (row < n) ? O[row * 96 + k] : 0.f;
    }
    __syncthreads();

#pragma unroll 8
    for (int k = 0; k < 96; k++) {
        const ull* b_ = (const ull*)&Bs[k * 48 + w * 4];
        ull bp0 = b_[0], bp1 = b_[1];
        const float* a_ = &As[k * 193 + lane];
#pragma unroll
        for (int f = 0; f < 6; f++) {
            float av = a_[f * 32];
            ull ap = pk2(av, av);
            acc[f][0] = fma2(ap, bp0, acc[f][0]);
            acc[f][1] = fma2(ap, bp1, acc[f][1]);
        }
    }

    float b1v[4], g2v[4];
#pragma unroll
    for (int jj = 0; jj < 4; jj++) {
        b1v[jj] = __ldg(&gb1[w * 4 + jj]);
        g2v[jj] = __ldg(&gw2[w * 4 + jj]);
    }
    float* sAl = sm;
    __syncthreads();
    for (int i = tid; i < 192; i += 384) sAl[i] = 0.f;
    __syncthreads();

#pragma unroll
    for (int f = 0; f < 6; f++) {
        int r = lane + f * 32;
        float h0, h1, h2, h3;
        upk2(acc[f][0], h0, h1);
        upk2(acc[f][1], h2, h3);
        float p = fmaxf(h0 + b1v[0], 0.f) * g2v[0]
                + fmaxf(h1 + b1v[1], 0.f) * g2v[1]
                + fmaxf(h2 + b1v[2], 0.f) * g2v[2]
                + fmaxf(h3 + b1v[3], 0.f) * g2v[3];
        atomicAdd(&sAl[r], p);
    }
    __syncthreads();
    float gb2v = __ldg(&gb2[0]);
    for (int i = tid; i < 192; i += 384) {
        int row = row0 + i;
        if (row < n) {
            float g = sAl[i] + gb2v;
            GATE[row] = g;
            atomicMaxF(&GM[__ldg(&batch[row])], g);
        }
    }
}

// ================= pooling: 8 blocks per graph; denom computed in-block =================
__global__ void k_pool2(const float* __restrict__ H, const float* __restrict__ GATE,
                        const float* __restrict__ GM, const int* __restrict__ batch,
                        float* __restrict__ POOL, int n) {
    __shared__ float red[192];
    __shared__ float sden;
    int g = blockIdx.x;
    int part = blockIdx.y;
    int tid = threadIdx.x;
    int lo = 0, hi = n;
    while (lo < hi) { int mid = (lo + hi) >> 1; if (__ldg(&batch[mid]) < g) lo = mid + 1; else hi = mid; }
    int beg = lo;
    lo = beg; hi = n;
    while (lo < hi) { int mid = (lo + hi) >> 1; if (__ldg(&batch[mid]) < g + 1) lo = mid + 1; else hi = mid; }
    int end = lo;

    float m = __ldg(&GM[g]);
    if (m == -INFINITY) m = 0.f;

    // denominator: all 192 threads sum over the whole segment
    float dsum = 0.f;
    for (int node = beg + tid; node < end; node += 192)
        dsum += __expf(__ldg(&GATE[node]) - m);
    red[tid] = dsum;
    __syncthreads();
    if (tid < 96) red[tid] += red[tid + 96];
    __syncthreads();
    if (tid < 32) {
        float v = red[tid] + red[tid + 32] + red[tid + 64];
#pragma unroll
        for (int o = 16; o > 0; o >>= 1) v += __shfl_xor_sync(0xffffffffu, v, o);
        if (tid == 0) sden = v;
    }
    __syncthreads();
    float invden = 1.f / (sden + 1e-16f);

    int half = tid / 96, c = tid - half * 96;
    float acc = 0.f;
    for (int node = beg + part * 2 + half; node < end; node += 16) {
        float wv = __expf(__ldg(&GATE[node]) - m) * invden;
        acc = fmaf(__ldg(&H[node * 96 + c]), wv, acc);
    }
    __syncthreads();
    red[tid] = acc;
    __syncthreads();
    if (tid < 96) POOL[(g * 8 + part) * 96 + tid] = red[tid] + red[tid + 96];
}

__global__ void k_final(const float* __restrict__ POOL, const float* __restrict__ fw1,
                        const float* __restrict__ fb1, const float* __restrict__ fw2,
                        const float* __restrict__ fb2, float* __restrict__ out) {
    __shared__ float pr[96];
    __shared__ float hid[96];
    int g = blockIdx.x, j = threadIdx.x;
    float p = 0.f;
#pragma unroll
    for (int q = 0; q < 8; q++) p += POOL[(g * 8 + q) * 96 + j];
    pr[j] = p;
    __syncthreads();
    float a = fb1[j];
#pragma unroll 8
    for (int k = 0; k < 96; k++) a += pr[k] * fw1[k * 96 + j];
    hid[j] = fmaxf(a, 0.f);
    __syncthreads();
    if (j < 3) {
        float o = fb2[j];
        for (int k = 0; k < 96; k++) o += hid[k] * fw2[k * 3 + j];
        out[g * 3 + j] = o;
    }
}

// ================= host =================
extern "C" void kernel_launch(void* const* d_in, const int* in_sizes, int n_in,
                              void* d_out, int out_size) {
    const float* x     = (const float*)d_in[0];
    const int*   ei    = (const int*)d_in[1];
    const int*   batch = (const int*)d_in[2];
    int idx = 3;
    if (n_in > 3 && in_sizes[3] == 1) idx = 4;
    const float* W1  = (const float*)d_in[idx++];
    const float* as1 = (const float*)d_in[idx++];
    const float* ad1 = (const float*)d_in[idx++];
    const float* b1  = (const float*)d_in[idx++];
    const float* W2  = (const float*)d_in[idx++];
    const float* as2 = (const float*)d_in[idx++];
    const float* ad2 = (const float*)d_in[idx++];
    const float* b2  = (const float*)d_in[idx++];
    const float* gw1 = (const float*)d_in[idx++];
    const float* gb1 = (const float*)d_in[idx++];
    const float* gw2 = (const float*)d_in[idx++];
    const float* gb2 = (const float*)d_in[idx++];
    const float* fw1 = (const float*)d_in[idx++];
    const float* fb1 = (const float*)d_in[idx++];
    const float* fw2 = (const float*)d_in[idx++];
    const float* fb2 = (const float*)d_in[idx++];

    int n    = in_sizes[0] / 128;
    int eraw = in_sizes[1] / 2;
    int etot = eraw + n;

    float *o, *as_, *ad_, *gate, *gm, *gden, *pool;
    __half2* h2;
    int *deg, *part, *bsum, *off, *srcs;
    cudaGetSymbolAddress((void**)&h2,   d_h2);
    cudaGetSymbolAddress((void**)&o,    d_o);
    cudaGetSymbolAddress((void**)&as_,  d_as);
    cudaGetSymbolAddress((void**)&ad_,  d_ad);
    cudaGetSymbolAddress((void**)&gate, d_gate);
    cudaGetSymbolAddress((void**)&gm,   d_gm);
    cudaGetSymbolAddress((void**)&gden, d_gden);
    cudaGetSymbolAddress((void**)&pool, d_pool);
    cudaGetSymbolAddress((void**)&deg,  d_deg);
    cudaGetSymbolAddress((void**)&part, d_part);
    cudaGetSymbolAddress((void**)&bsum, d_bsum);
    cudaGetSymbolAddress((void**)&off,  d_off);
    cudaGetSymbolAddress((void**)&srcs, d_srcs);

    int smem1 = 128 * 96 * 4 + 64 * 194 * 2;   // Bs fp32 + Ah fp16
    int smem2 = 96 * 96 * 4 + 96 * 194 * 2;
    int smemG = (96 * 48 + 96 * 193) * 4;
    cudaFuncSetAttribute(k_gemm2<128, 64>, cudaFuncAttributeMaxDynamicSharedMemorySize, smem1);
    cudaFuncSetAttribute(k_gemm2<96, 96>,  cudaFuncAttributeMaxDynamicSharedMemorySize, smem2);
    cudaFuncSetAttribute(k_gateg,          cudaFuncAttributeMaxDynamicSharedMemorySize, smemG);

    int gEdge  = (etot + 255) / 256;
    int gWarp  = (n * 32 + 255) / 256;
    int gGemm  = (n + 191) / 192;
    int gScan  = (n + 1023) / 1024;

    // side stream + events (created once, outside any graph capture)
    static cudaStream_t s1 = nullptr;
    static cudaEvent_t evFork = nullptr, evJoin = nullptr;
    if (s1 == nullptr) {
        cudaStreamCreateWithFlags(&s1, cudaStreamNonBlocking);
        cudaEventCreateWithFlags(&evFork, cudaEventDisableTiming);
        cudaEventCreateWithFlags(&evJoin, cudaEventDisableTiming);
    }

    // ---- fork: CSR build on side stream, layer-1 GEMM on main stream ----
    cudaEventRecord(evFork, 0);
    cudaStreamWaitEvent(s1, evFork, 0);

    cudaMemsetAsync(deg, 0, n * sizeof(int), s1);
    k_hist<<<gEdge, 256, 0, s1>>>(ei, deg, etot, eraw);
    k_scanA<<<gScan, 1024, 0, s1>>>(deg, part, bsum, n);
    k_scanB<<<1, 64, 0, s1>>>(bsum, gScan);
    k_scanC<<<gScan, 1024, 0, s1>>>(part, bsum, off, deg, gm, gden, n, etot);
    k_scatter<<<gEdge, 256, 0, s1>>>(ei, deg, srcs, etot, eraw);
    cudaEventRecord(evJoin, s1);

    k_gemm2<128, 64><<<gGemm, 384, smem1>>>(x, W1, as1, ad1, h2, as_, ad_, n);

    // ---- join, then edge phase ----
    cudaStreamWaitEvent(0, evJoin, 0);
    k_sagg<<<gWarp, 256>>>(off, srcs, as_, ad_, h2, b1, o, n);

    // ---- layer 2 ----
    k_gemm2<96, 96><<<gGemm, 384, smem2>>>(o, W2, as2, ad2, h2, as_, ad_, n);
    k_sagg<<<gWarp, 256>>>(off, srcs, as_, ad_, h2, b2, o, n);

    // ---- global attention pool + final MLP ----
    k_gateg<<<gGemm, 384, smemG>>>(o, gw1, gb1, gw2, gb2, batch, gate, gm, n);
    k_pool2<<<dim3(GG, 8), 192>>>(o, gate, gm, batch, pool, n);
    k_final<<<GG, 96>>>(pool, fw1, fb1, fw2, fb2, (float*)d_out);
}

// round 13
// speedup vs baseline: 1.4400x; 1.1760x over previous
#include <cuda_runtime.h>
#include <cuda_fp16.h>
#include <mma.h>
#include <math.h>

using namespace nvcuda;

#define NN 50000
#define EE 800000
#define ETOT (EE + NN)
#define GG 64

// ---------------- scratch ----------------
__device__ __half2 d_h2[NN * 48];   // fp16 message matrix (H), 48 half2 per row
__device__ float d_o[NN * 96];
__device__ float d_as[NN * 4];
__device__ float d_ad[NN * 4];
__device__ int   d_deg[NN];
__device__ int   d_part[NN];
__device__ int   d_bsum[64];
__device__ int   d_off[NN + 1];
__device__ int   d_srcs[ETOT];
__device__ float d_gate[NN];
__device__ float d_gm[GG];
__device__ float d_gden[GG];
__device__ float d_pool[GG * 8 * 96];

__device__ __forceinline__ void atomicMaxF(float* a, float v) {
    if (v >= 0.f) atomicMax((int*)a, __float_as_int(v));
    else          atomicMin((unsigned int*)a, __float_as_uint(v));
}

typedef unsigned long long ull;
__device__ __forceinline__ ull pk2(float x, float y) {
    ull r;
    asm("mov.b64 %0, {%1, %2};" : "=l"(r) : "f"(x), "f"(y));
    return r;
}
__device__ __forceinline__ ull fma2(ull a, ull b, ull c) {
    ull d;
    asm("fma.rn.f32x2 %0, %1, %2, %3;" : "=l"(d) : "l"(a), "l"(b), "l"(c));
    return d;
}
__device__ __forceinline__ void upk2(ull v, float& x, float& y) {
    asm("mov.b64 {%0, %1}, %2;" : "=f"(x), "=f"(y) : "l"(v));
}

// ================= CSR build =================
__global__ void k_hist(const int* __restrict__ ei, int* __restrict__ deg, int etot, int eraw) {
    int e = blockIdx.x * blockDim.x + threadIdx.x;
    if (e >= etot) return;
    int d = (e < eraw) ? __ldg(&ei[eraw + e]) : e - eraw;
    atomicAdd(&deg[d], 1);
}

__global__ void k_scanA(const int* __restrict__ deg, int* __restrict__ part,
                        int* __restrict__ bsum, int n) {
    __shared__ int wsum[32];
    int t = threadIdx.x;
    int i = blockIdx.x * 1024 + t;
    int v = (i < n) ? deg[i] : 0;
    int lane = t & 31, w = t >> 5;
    int x = v;
#pragma unroll
    for (int o = 1; o < 32; o <<= 1) {
        int y = __shfl_up_sync(0xffffffffu, x, o);
        if (lane >= o) x += y;
    }
    if (lane == 31) wsum[w] = x;
    __syncthreads();
    if (w == 0) {
        int s = wsum[lane];
#pragma unroll
        for (int o = 1; o < 32; o <<= 1) {
            int y = __shfl_up_sync(0xffffffffu, s, o);
            if (lane >= o) s += y;
        }
        wsum[lane] = s;
    }
    __syncthreads();
    int woff = (w > 0) ? wsum[w - 1] : 0;
    if (i < n) part[i] = x - v + woff;
    if (t == 0) bsum[blockIdx.x] = wsum[31];
}

__global__ void k_scanB(int* __restrict__ bsum, int nb) {
    __shared__ int w0tot;
    int t = threadIdx.x;
    int lane = t & 31, w = t >> 5;
    int v = (t < nb) ? bsum[t] : 0;
    int x = v;
#pragma unroll
    for (int o = 1; o < 32; o <<= 1) {
        int y = __shfl_up_sync(0xffffffffu, x, o);
        if (lane >= o) x += y;
    }
    if (w == 0 && lane == 31) w0tot = x;
    __syncthreads();
    if (w == 1) x += w0tot;
    if (t < nb) bsum[t] = x - v;
}

__global__ void k_scanC(const int* __restrict__ part, const int* __restrict__ bsum,
                        int* __restrict__ off, int* __restrict__ cur,
                        float* __restrict__ GM, float* __restrict__ GDEN,
                        int n, int etot) {
    int i = blockIdx.x * 1024 + threadIdx.x;
    if (i < n) {
        int v = part[i] + bsum[blockIdx.x];
        off[i] = v;
        cur[i] = v;
    }
    if (i == 0) off[n] = etot;
    if (blockIdx.x == 0 && threadIdx.x < GG) {
        GM[threadIdx.x] = -INFINITY;
        GDEN[threadIdx.x] = 0.f;
    }
}

__global__ void k_scatter(const int* __restrict__ ei, int* __restrict__ cur,
                          int* __restrict__ srcs, int etot, int eraw) {
    int e = blockIdx.x * blockDim.x + threadIdx.x;
    if (e >= etot) return;
    int s, d;
    if (e < eraw) { s = __ldg(&ei[e]); d = __ldg(&ei[eraw + e]); }
    else          { s = d = e - eraw; }
    int pos = atomicAdd(&cur[d], 1);
    srcs[pos] = s;
}

// ================= Tensor-core GEMM + fused alpha epilogue =================
// C[n,96] = A[n,K]@W[K,96] in fp16 (fp32 accum). 128-row tile, 256 thr / 8 warps.
// Warp w owns rows [16w,16w+16), iterates 6 col-groups of m16n16k16 HMMA.
// Cs (fp32 result) aliases the Ah/Wh staging region after a sync.
template<int K>
__global__ void __launch_bounds__(256, 2) k_gemmT(const float* __restrict__ A,
                                                  const float* __restrict__ W,
                                                  const float* __restrict__ asrc,
                                                  const float* __restrict__ adst,
                                                  __half2* __restrict__ H2,
                                                  float* __restrict__ AS,
                                                  float* __restrict__ AD, int n) {
    extern __shared__ char smc[];
    const int SA = K + 8, SB = 104, SC = 100;
    __half* Ah = (__half*)smc;                    // 128 x SA
    __half* Wh = (__half*)smc + 128 * SA;         // K x SB
    float*  Cs = (float*)smc;                     // alias: 128 x SC
    __shared__ float s_as[96], s_ad[96];

    int tid = threadIdx.x, w = tid >> 5;
    int row0 = blockIdx.x * 128;

    if (tid < 96) { s_as[tid] = __ldg(&asrc[tid]); s_ad[tid] = __ldg(&adst[tid]); }

    for (int i = tid; i < 128 * K; i += 256) {
        int r = i / K, c = i - r * K;
        int row = row0 + r;
        Ah[r * SA + c] = (row < n) ? __float2half(A[(size_t)row * K + c]) : __half(0.f);
    }
    for (int i = tid; i < K * 96; i += 256) {
        int k = i / 96, c = i - k * 96;
        Wh[k * SB + c] = __float2half(W[i]);
    }
    __syncthreads();

    wmma::fragment<wmma::accumulator, 16, 16, 16, float> cf[6];
#pragma unroll
    for (int cg = 0; cg < 6; cg++) wmma::fill_fragment(cf[cg], 0.f);
    wmma::fragment<wmma::matrix_a, 16, 16, 16, __half, wmma::row_major> af;
    wmma::fragment<wmma::matrix_b, 16, 16, 16, __half, wmma::row_major> bf;
#pragma unroll
    for (int ks = 0; ks < K / 16; ks++) {
        wmma::load_matrix_sync(af, Ah + w * 16 * SA + ks * 16, SA);
#pragma unroll
        for (int cg = 0; cg < 6; cg++) {
            wmma::load_matrix_sync(bf, Wh + ks * 16 * SB + cg * 16, SB);
            wmma::mma_sync(cf[cg], af, bf, cf[cg]);
        }
    }
    __syncthreads();   // all warps done reading Ah/Wh -> safe to alias Cs
#pragma unroll
    for (int cg = 0; cg < 6; cg++)
        wmma::store_matrix_sync(Cs + w * 16 * SC + cg * 16, cf[cg], SC, wmma::mem_row_major);
    __syncthreads();

    // epilogue: 2 threads per row; thread handles 48 cols = 2 whole heads
    int row = tid >> 1, hv = tid & 1;
    int grow = row0 + row;
    if (grow < n) {
        const float* cr = Cs + row * SC + hv * 48;
        int h0 = hv * 2;
        const float* as0 = s_as + h0 * 24;
        const float* ad0 = s_ad + h0 * 24;
        union { __half2 h[24]; uint4 u[6]; } pk;
        float sp0 = 0.f, dp0 = 0.f, sp1 = 0.f, dp1 = 0.f;
#pragma unroll
        for (int j = 0; j < 12; j++) {
            float ca = cr[2 * j], cb = cr[2 * j + 1];
            pk.h[j] = __floats2half2_rn(ca, cb);
            sp0 += ca * as0[2 * j] + cb * as0[2 * j + 1];
            dp0 += ca * ad0[2 * j] + cb * ad0[2 * j + 1];
        }
#pragma unroll
        for (int j = 12; j < 24; j++) {
            float ca = cr[2 * j], cb = cr[2 * j + 1];
            pk.h[j] = __floats2half2_rn(ca, cb);
            int jj = 2 * j - 24;
            sp1 += ca * as0[24 + jj] + cb * as0[24 + jj + 1];
            dp1 += ca * ad0[24 + jj] + cb * ad0[24 + jj + 1];
        }
        uint4* dst = (uint4*)(H2 + (size_t)grow * 48 + hv * 24);
#pragma unroll
        for (int q = 0; q < 6; q++) dst[q] = pk.u[q];
        AS[grow * 4 + h0]     = sp0;
        AS[grow * 4 + h0 + 1] = sp1;
        AD[grow * 4 + h0]     = dp0;
        AD[grow * 4 + h0 + 1] = dp1;
    }
}

// ================= fused softmax + aggregation (warp per dst, fp16 H gather) =================
#define DCAP 128
__global__ void k_sagg(const int* __restrict__ off, const int* __restrict__ srcs,
                       const float* __restrict__ AS, const float* __restrict__ AD,
                       const __half2* __restrict__ H2, const float* __restrict__ bias,
                       float* __restrict__ OUT, int n) {
    __shared__ int    ssrc[8][DCAP];
    __shared__ float4 slog[8][DCAP];
    int gtid = blockIdx.x * blockDim.x + threadIdx.x;
    int node = gtid >> 5, lane = gtid & 31;
    int ws = threadIdx.x >> 5;
    if (node >= n) return;
    int beg = __ldg(&off[node]), end = __ldg(&off[node + 1]);
    int deg = end - beg;
    float4 ad = *(const float4*)(AD + node * 4);

    bool act = lane < 24;
    int head = lane / 6;
    float4 acc = make_float4(0.f, 0.f, 0.f, 0.f);
    float4 den = make_float4(0.f, 0.f, 0.f, 0.f);
    float4 mx = make_float4(-INFINITY, -INFINITY, -INFINITY, -INFINITY);

    if (deg <= DCAP) {
        for (int j = lane; j < deg; j += 32) {
            int s = __ldg(&srcs[beg + j]);
            float4 a = *(const float4*)(AS + s * 4);
            float t; float4 v;
            t = a.x + ad.x; v.x = t > 0.f ? t : 0.2f * t; mx.x = fmaxf(mx.x, v.x);
            t = a.y + ad.y; v.y = t > 0.f ? t : 0.2f * t; mx.y = fmaxf(mx.y, v.y);
            t = a.z + ad.z; v.z = t > 0.f ? t : 0.2f * t; mx.z = fmaxf(mx.z, v.z);
            t = a.w + ad.w; v.w = t > 0.f ? t : 0.2f * t; mx.w = fmaxf(mx.w, v.w);
            ssrc[ws][j] = s;
            slog[ws][j] = v;
        }
#pragma unroll
        for (int o = 16; o > 0; o >>= 1) {
            mx.x = fmaxf(mx.x, __shfl_xor_sync(0xffffffffu, mx.x, o));
            mx.y = fmaxf(mx.y, __shfl_xor_sync(0xffffffffu, mx.y, o));
            mx.z = fmaxf(mx.z, __shfl_xor_sync(0xffffffffu, mx.z, o));
            mx.w = fmaxf(mx.w, __shfl_xor_sync(0xffffffffu, mx.w, o));
        }
        __syncwarp();
        for (int j = lane; j < deg; j += 32) {
            float4 v = slog[ws][j];
            float4 ex;
            ex.x = __expf(v.x - mx.x); ex.y = __expf(v.y - mx.y);
            ex.z = __expf(v.z - mx.z); ex.w = __expf(v.w - mx.w);
            slog[ws][j] = ex;
            den.x += ex.x; den.y += ex.y; den.z += ex.z; den.w += ex.w;
        }
        __syncwarp();
        if (act) {
            const float* sexf = (const float*)&slog[ws][0];
#pragma unroll 4
            for (int j = 0; j < deg; j++) {
                int s = ssrc[ws][j];
                float wv = sexf[j * 4 + head];
                uint2 raw = __ldg((const uint2*)(H2 + s * 48) + lane);
                float2 f01 = __half22float2(*(__half2*)&raw.x);
                float2 f23 = __half22float2(*(__half2*)&raw.y);
                acc.x = fmaf(f01.x, wv, acc.x);
                acc.y = fmaf(f01.y, wv, acc.y);
                acc.z = fmaf(f23.x, wv, acc.z);
                acc.w = fmaf(f23.y, wv, acc.w);
            }
        }
    } else {
        for (int e = beg + lane; e < end; e += 32) {
            int s = __ldg(&srcs[e]);
            float4 a = *(const float4*)(AS + s * 4);
            float t;
            t = a.x + ad.x; t = t > 0.f ? t : 0.2f * t; mx.x = fmaxf(mx.x, t);
            t = a.y + ad.y; t = t > 0.f ? t : 0.2f * t; mx.y = fmaxf(mx.y, t);
            t = a.z + ad.z; t = t > 0.f ? t : 0.2f * t; mx.z = fmaxf(mx.z, t);
            t = a.w + ad.w; t = t > 0.f ? t : 0.2f * t; mx.w = fmaxf(mx.w, t);
        }
#pragma unroll
        for (int o = 16; o > 0; o >>= 1) {
            mx.x = fmaxf(mx.x, __shfl_xor_sync(0xffffffffu, mx.x, o));
            mx.y = fmaxf(mx.y, __shfl_xor_sync(0xffffffffu, mx.y, o));
            mx.z = fmaxf(mx.z, __shfl_xor_sync(0xffffffffu, mx.z, o));
            mx.w = fmaxf(mx.w, __shfl_xor_sync(0xffffffffu, mx.w, o));
        }
        for (int c0 = beg; c0 < end; c0 += 32) {
            int e = c0 + lane;
            if (e < end) {
                int s = __ldg(&srcs[e]);
                float4 a = *(const float4*)(AS + s * 4);
                float t; float4 ex;
                t = a.x + ad.x; t = t > 0.f ? t : 0.2f * t; ex.x = __expf(t - mx.x);
                t = a.y + ad.y; t = t > 0.f ? t : 0.2f * t; ex.y = __expf(t - mx.y);
                t = a.z + ad.z; t = t > 0.f ? t : 0.2f * t; ex.z = __expf(t - mx.z);
                t = a.w + ad.w; t = t > 0.f ? t : 0.2f * t; ex.w = __expf(t - mx.w);
                den.x += ex.x; den.y += ex.y; den.z += ex.z; den.w += ex.w;
                ssrc[ws][lane] = s;
                slog[ws][lane] = ex;
            }
            __syncwarp();
            int cnt = min(32, end - c0);
            if (act) {
                const float* sexf = (const float*)&slog[ws][0];
                for (int j = 0; j < cnt; j++) {
                    int s = ssrc[ws][j];
                    float wv = sexf[j * 4 + head];
                    uint2 raw = __ldg((const uint2*)(H2 + s * 48) + lane);
                    float2 f01 = __half22float2(*(__half2*)&raw.x);
                    float2 f23 = __half22float2(*(__half2*)&raw.y);
                    acc.x = fmaf(f01.x, wv, acc.x);
                    acc.y = fmaf(f01.y, wv, acc.y);
                    acc.z = fmaf(f23.x, wv, acc.z);
                    acc.w = fmaf(f23.y, wv, acc.w);
                }
            }
            __syncwarp();
        }
    }

#pragma unroll
    for (int o = 16; o > 0; o >>= 1) {
        den.x += __shfl_xor_sync(0xffffffffu, den.x, o);
        den.y += __shfl_xor_sync(0xffffffffu, den.y, o);
        den.z += __shfl_xor_sync(0xffffffffu, den.z, o);
        den.w += __shfl_xor_sync(0xffffffffu, den.w, o);
    }
    if (act) {
        float dh = head == 0 ? den.x : (head == 1 ? den.y : (head == 2 ? den.z : den.w));
        float inv = 1.f / (dh + 1e-16f);
        float4 b4 = *(const float4*)(bias + lane * 4);
        float4 o;
        o.x = acc.x * inv + b4.x;  o.x = o.x > 0.f ? o.x : expm1f(o.x);
        o.y = acc.y * inv + b4.y;  o.y = o.y > 0.f ? o.y : expm1f(o.y);
        o.z = acc.z * inv + b4.z;  o.z = o.z > 0.f ? o.z : expm1f(o.z);
        o.w = acc.w * inv + b4.w;  o.w = o.w > 0.f ? o.w : expm1f(o.w);
        *(float4*)(OUT + node * 96 + lane * 4) = o;
    }
}

// ================= gate MLP as GEMM: [n,96]@[96,48] -> relu -> ·gw2 =================
__global__ void __launch_bounds__(384, 2) k_gateg(const float* __restrict__ O,
                                                  const float* __restrict__ gw1,
                                                  const float* __restrict__ gb1,
                                                  const float* __restrict__ gw2,
                                                  const float* __restrict__ gb2,
                                                  const int* __restrict__ batch,
                                                  float* __restrict__ GATE,
                                                  float* __restrict__ GM, int n) {
    extern __shared__ float sm[];
    float* Bs = sm;              // 96*48
    float* As = sm + 96 * 48;    // 96*193
    int tid = threadIdx.x;
    int w = tid >> 5, lane = tid & 31;
    int row0 = blockIdx.x * 192;

    ull acc[6][2];
#pragma unroll
    for (int f = 0; f < 6; f++) { acc[f][0] = 0ull; acc[f][1] = 0ull; }

    for (int i = tid; i < 96 * 48; i += 384) Bs[i] = gw1[i];
    for (int i = tid; i < 192 * 96; i += 384) {
        int k = i % 96, r = i / 96;
        int row = row0 + r;
        As[k * 193 + r] = (row < n) ? O[row * 96 + k] : 0.f;
    }
    __syncthreads();

#pragma unroll 8
    for (int k = 0; k < 96; k++) {
        const ull* b_ = (const ull*)&Bs[k * 48 + w * 4];
        ull bp0 = b_[0], bp1 = b_[1];
        const float* a_ = &As[k * 193 + lane];
#pragma unroll
        for (int f = 0; f < 6; f++) {
            float av = a_[f * 32];
            ull ap = pk2(av, av);
            acc[f][0] = fma2(ap, bp0, acc[f][0]);
            acc[f][1] = fma2(ap, bp1, acc[f][1]);
        }
    }

    float b1v[4], g2v[4];
#pragma unroll
    for (int jj = 0; jj < 4; jj++) {
        b1v[jj] = __ldg(&gb1[w * 4 + jj]);
        g2v[jj] = __ldg(&gw2[w * 4 + jj]);
    }
    float* sAl = sm;
    __syncthreads();
    for (int i = tid; i < 192; i += 384) sAl[i] = 0.f;
    __syncthreads();

#pragma unroll
    for (int f = 0; f < 6; f++) {
        int r = lane + f * 32;
        float h0, h1, h2, h3;
        upk2(acc[f][0], h0, h1);
        upk2(acc[f][1], h2, h3);
        float p = fmaxf(h0 + b1v[0], 0.f) * g2v[0]
                + fmaxf(h1 + b1v[1], 0.f) * g2v[1]
                + fmaxf(h2 + b1v[2], 0.f) * g2v[2]
                + fmaxf(h3 + b1v[3], 0.f) * g2v[3];
        atomicAdd(&sAl[r], p);
    }
    __syncthreads();
    float gb2v = __ldg(&gb2[0]);
    for (int i = tid; i < 192; i += 384) {
        int row = row0 + i;
        if (row < n) {
            float g = sAl[i] + gb2v;
            GATE[row] = g;
            atomicMaxF(&GM[__ldg(&batch[row])], g);
        }
    }
}

// ================= pooling: 8 blocks per graph; denom computed in-block =================
__global__ void k_pool2(const float* __restrict__ H, const float* __restrict__ GATE,
                        const float* __restrict__ GM, const int* __restrict__ batch,
                        float* __restrict__ POOL, int n) {
    __shared__ float red[192];
    __shared__ float sden;
    int g = blockIdx.x;
    int part = blockIdx.y;
    int tid = threadIdx.x;
    int lo = 0, hi = n;
    while (lo < hi) { int mid = (lo + hi) >> 1; if (__ldg(&batch[mid]) < g) lo = mid + 1; else hi = mid; }
    int beg = lo;
    lo = beg; hi = n;
    while (lo < hi) { int mid = (lo + hi) >> 1; if (__ldg(&batch[mid]) < g + 1) lo = mid + 1; else hi = mid; }
    int end = lo;

    float m = __ldg(&GM[g]);
    if (m == -INFINITY) m = 0.f;

    float dsum = 0.f;
    for (int node = beg + tid; node < end; node += 192)
        dsum += __expf(__ldg(&GATE[node]) - m);
    red[tid] = dsum;
    __syncthreads();
    if (tid < 96) red[tid] += red[tid + 96];
    __syncthreads();
    if (tid < 32) {
        float v = red[tid] + red[tid + 32] + red[tid + 64];
#pragma unroll
        for (int o = 16; o > 0; o >>= 1) v += __shfl_xor_sync(0xffffffffu, v, o);
        if (tid == 0) sden = v;
    }
    __syncthreads();
    float invden = 1.f / (sden + 1e-16f);

    int half = tid / 96, c = tid - half * 96;
    float acc = 0.f;
    for (int node = beg + part * 2 + half; node < end; node += 16) {
        float wv = __expf(__ldg(&GATE[node]) - m) * invden;
        acc = fmaf(__ldg(&H[node * 96 + c]), wv, acc);
    }
    __syncthreads();
    red[tid] = acc;
    __syncthreads();
    if (tid < 96) POOL[(g * 8 + part) * 96 + tid] = red[tid] + red[tid + 96];
}

__global__ void k_final(const float* __restrict__ POOL, const float* __restrict__ fw1,
                        const float* __restrict__ fb1, const float* __restrict__ fw2,
                        const float* __restrict__ fb2, float* __restrict__ out) {
    __shared__ float pr[96];
    __shared__ float hid[96];
    int g = blockIdx.x, j = threadIdx.x;
    float p = 0.f;
#pragma unroll
    for (int q = 0; q < 8; q++) p += POOL[(g * 8 + q) * 96 + j];
    pr[j] = p;
    __syncthreads();
    float a = fb1[j];
#pragma unroll 8
    for (int k = 0; k < 96; k++) a += pr[k] * fw1[k * 96 + j];
    hid[j] = fmaxf(a, 0.f);
    __syncthreads();
    if (j < 3) {
        float o = fb2[j];
        for (int k = 0; k < 96; k++) o += hid[k] * fw2[k * 3 + j];
        out[g * 3 + j] = o;
    }
}

// ================= host =================
extern "C" void kernel_launch(void* const* d_in, const int* in_sizes, int n_in,
                              void* d_out, int out_size) {
    const float* x     = (const float*)d_in[0];
    const int*   ei    = (const int*)d_in[1];
    const int*   batch = (const int*)d_in[2];
    int idx = 3;
    if (n_in > 3 && in_sizes[3] == 1) idx = 4;
    const float* W1  = (const float*)d_in[idx++];
    const float* as1 = (const float*)d_in[idx++];
    const float* ad1 = (const float*)d_in[idx++];
    const float* b1  = (const float*)d_in[idx++];
    const float* W2  = (const float*)d_in[idx++];
    const float* as2 = (const float*)d_in[idx++];
    const float* ad2 = (const float*)d_in[idx++];
    const float* b2  = (const float*)d_in[idx++];
    const float* gw1 = (const float*)d_in[idx++];
    const float* gb1 = (const float*)d_in[idx++];
    const float* gw2 = (const float*)d_in[idx++];
    const float* gb2 = (const float*)d_in[idx++];
    const float* fw1 = (const float*)d_in[idx++];
    const float* fb1 = (const float*)d_in[idx++];
    const float* fw2 = (const float*)d_in[idx++];
    const float* fb2 = (const float*)d_in[idx++];

    int n    = in_sizes[0] / 128;
    int eraw = in_sizes[1] / 2;
    int etot = eraw + n;

    float *o, *as_, *ad_, *gate, *gm, *gden, *pool;
    __half2* h2;
    int *deg, *part, *bsum, *off, *srcs;
    cudaGetSymbolAddress((void**)&h2,   d_h2);
    cudaGetSymbolAddress((void**)&o,    d_o);
    cudaGetSymbolAddress((void**)&as_,  d_as);
    cudaGetSymbolAddress((void**)&ad_,  d_ad);
    cudaGetSymbolAddress((void**)&gate, d_gate);
    cudaGetSymbolAddress((void**)&gm,   d_gm);
    cudaGetSymbolAddress((void**)&gden, d_gden);
    cudaGetSymbolAddress((void**)&pool, d_pool);
    cudaGetSymbolAddress((void**)&deg,  d_deg);
    cudaGetSymbolAddress((void**)&part, d_part);
    cudaGetSymbolAddress((void**)&bsum, d_bsum);
    cudaGetSymbolAddress((void**)&off,  d_off);
    cudaGetSymbolAddress((void**)&srcs, d_srcs);

    // smem: stage1 = Ah(128*(K+8)) + Wh(K*104) halfs; Cs alias = 128*100 floats
    int smem1 = 128 * (128 + 8) * 2 + 128 * 104 * 2;   // 61440
    int smem2 = 128 * 100 * 4;                          // 51200 (> Ah+Wh for K=96)
    int smemG = (96 * 48 + 96 * 193) * 4;
    cudaFuncSetAttribute(k_gemmT<128>, cudaFuncAttributeMaxDynamicSharedMemorySize, smem1);
    cudaFuncSetAttribute(k_gemmT<96>,  cudaFuncAttributeMaxDynamicSharedMemorySize, smem2);
    cudaFuncSetAttribute(k_gateg,      cudaFuncAttributeMaxDynamicSharedMemorySize, smemG);

    int gEdge  = (etot + 255) / 256;
    int gWarp  = (n * 32 + 255) / 256;
    int gGemm  = (n + 127) / 128;
    int gGate  = (n + 191) / 192;
    int gScan  = (n + 1023) / 1024;

    // side stream + events (created once, outside any graph capture)
    static cudaStream_t s1 = nullptr;
    static cudaEvent_t evFork = nullptr, evJoin = nullptr;
    if (s1 == nullptr) {
        cudaStreamCreateWithFlags(&s1, cudaStreamNonBlocking);
        cudaEventCreateWithFlags(&evFork, cudaEventDisableTiming);
        cudaEventCreateWithFlags(&evJoin, cudaEventDisableTiming);
    }

    // ---- fork: CSR build on side stream, layer-1 GEMM on main stream ----
    cudaEventRecord(evFork, 0);
    cudaStreamWaitEvent(s1, evFork, 0);

    cudaMemsetAsync(deg, 0, n * sizeof(int), s1);
    k_hist<<<gEdge, 256, 0, s1>>>(ei, deg, etot, eraw);
    k_scanA<<<gScan, 1024, 0, s1>>>(deg, part, bsum, n);
    k_scanB<<<1, 64, 0, s1>>>(bsum, gScan);
    k_scanC<<<gScan, 1024, 0, s1>>>(part, bsum, off, deg, gm, gden, n, etot);
    k_scatter<<<gEdge, 256, 0, s1>>>(ei, deg, srcs, etot, eraw);
    cudaEventRecord(evJoin, s1);

    k_gemmT<128><<<gGemm, 256, smem1>>>(x, W1, as1, ad1, h2, as_, ad_, n);

    // ---- join, then edge phase ----
    cudaStreamWaitEvent(0, evJoin, 0);
    k_sagg<<<gWarp, 256>>>(off, srcs, as_, ad_, h2, b1, o, n);

    // ---- layer 2 ----
    k_gemmT<96><<<gGemm, 256, smem2>>>(o, W2, as2, ad2, h2, as_, ad_, n);
    k_sagg<<<gWarp, 256>>>(off, srcs, as_, ad_, h2, b2, o, n);

    // ---- global attention pool + final MLP ----
    k_gateg<<<gGate, 384, smemG>>>(o, gw1, gb1, gw2, gb2, batch, gate, gm, n);
    k_pool2<<<dim3(GG, 8), 192>>>(o, gate, gm, batch, pool, n);
    k_final<<<GG, 96>>>(pool, fw1, fb1, fw2, fb2, (float*)d_out);
}